// round 12
// baseline (speedup 1.0000x reference)
#include <cuda_runtime.h>
#include <math.h>
#include <stdint.h>

// Problem constants
#define H   516
#define T   512
#define B   64
#define NY  20
#define SEQ 20
#define G4  2064      /* 4*H */
#define H2  1032      /* 2*H */
#define TB  32768     /* T*B */
#define G8  4128      /* 2*G4 */

// ------------------------- scratch (device globals) -------------------------
__device__ float g_Gx[TB * G8];             // [t*B+b][dir*G4 + j]  (interleaved)
__device__ float g_out0[TB * H2];
__device__ float g_outenc[TB * H2];
__device__ float g_E2[TB * H2];
__device__ float g_Wc[G8 * 4];              // folded layer0 input weights
__device__ float g_bc[G8];                  // folded layer0 bias
__device__ float g_eh[2 * 2 * B * H];       // [parity][dir][B][H]
__device__ float g_ec[2 * 2 * B * H];
__device__ float g_dh[2 * 4 * B * H];       // [parity][slot4][B][H]
__device__ float g_dc[2 * 4 * B * H];
__device__ float g_l0[B * H2];
__device__ float g_cc[B * 2 * H2];          // [outdec | context]
__device__ float g_dbuf[B * H2];
__device__ float g_co[B * H2];
__device__ float g_score[B * T];
__device__ float g_loss[1];
__device__ unsigned g_bcount = 0;
__device__ unsigned g_bgen = 0;

// --------------------------- packed helpers ---------------------------------
__device__ __forceinline__ void fma2(unsigned long long& d,
                                     unsigned long long a,
                                     unsigned long long b) {
    asm("fma.rn.f32x2 %0, %1, %2, %0;" : "+l"(d) : "l"(a), "l"(b));
}
__device__ __forceinline__ unsigned long long pack2(float lo, float hi) {
    unsigned long long r;
    asm("mov.b64 %0, {%1, %2};" : "=l"(r) : "f"(lo), "f"(hi));
    return r;
}
__device__ __forceinline__ void unpack2(unsigned long long v, float& lo, float& hi) {
    asm("mov.b64 {%0, %1}, %2;" : "=f"(lo), "=f"(hi) : "l"(v));
}
__device__ __forceinline__ uint32_t to_tf32(float x) {
    uint32_t r;
    asm("cvt.rna.tf32.f32 %0, %1;" : "=r"(r) : "f"(x));
    return r;
}
__device__ __forceinline__ float ftanh(float x) {
    float r;
    asm("tanh.approx.f32 %0, %1;" : "=f"(r) : "f"(x));
    return r;
}

// -------------------------- software grid barrier ---------------------------
__device__ __forceinline__ void grid_barrier(unsigned nb) {
    __syncthreads();
    if (threadIdx.x == 0) {
        __threadfence();
        unsigned gen = *(volatile unsigned*)&g_bgen;
        if (atomicAdd(&g_bcount, 1) == nb - 1) {
            atomicExch(&g_bcount, 0);
            __threadfence();
            atomicAdd(&g_bgen, 1);
        } else {
            while (*(volatile unsigned*)&g_bgen == gen) {}
        }
        __threadfence();
    }
    __syncthreads();
}

// ------------------------------ small kernels -------------------------------
__global__ void zero_kernel(float* p, int n) {
    int i = blockIdx.x * 256 + threadIdx.x;
    if (i < n) p[i] = 0.f;
}

__global__ void write_out_kernel(float* out, const float* loss) {
    out[0] = loss[0];
}

__global__ void copy2_kernel(const float* sh, const float* sc,
                             float* dh, float* dc, int n) {
    int i = blockIdx.x * 256 + threadIdx.x;
    if (i < n) { dh[i] = sh[i]; dc[i] = sc[i]; }
}

// Wc = eWi0 @ expand_W  (G8 x 4), bc = eWi0 @ expand_b + eb0
__global__ void fold0_kernel(const float* __restrict__ eWi0,   // [G8][256]
                             const float* __restrict__ We,     // [256][4]
                             const float* __restrict__ be,     // [256]
                             const float* __restrict__ eb0,    // [G8]
                             float* __restrict__ Wc,
                             float* __restrict__ bc) {
    int i = blockIdx.x * 128 + threadIdx.x;
    if (i >= G8) return;
    const float* wi = eWi0 + (size_t)i * 256;
    float a0 = 0.f, a1 = 0.f, a2 = 0.f, a3 = 0.f, ab = eb0[i];
    for (int k = 0; k < 256; k++) {
        float w = wi[k];
        float4 we4 = *(const float4*)(We + k * 4);
        a0 = fmaf(w, we4.x, a0);
        a1 = fmaf(w, we4.y, a1);
        a2 = fmaf(w, we4.z, a2);
        a3 = fmaf(w, we4.w, a3);
        ab = fmaf(w, be[k], ab);
    }
    *(float4*)(Wc + (size_t)i * 4) = make_float4(a0, a1, a2, a3);
    bc[i] = ab;
}

// Gx = x @ Wc^T + bc   (K = 4). grid (33, TB/64), 256 threads.
__global__ void gx0_kernel(const float* __restrict__ x,      // [TB][4]
                           const float* __restrict__ Wc,     // [G8][4]
                           const float* __restrict__ bc,     // [G8]
                           float* __restrict__ Gx) {         // [TB][G8]
    __shared__ float4 xs[64];
    __shared__ float4 ws[128];
    __shared__ float bs[128];
    int tid = threadIdx.x;
    int r0 = blockIdx.y * 64, c0 = blockIdx.x * 128;
    if (tid < 64) xs[tid] = *(const float4*)(x + (size_t)(r0 + tid) * 4);
    if (tid >= 128) {
        int q = tid - 128;
        int c = c0 + q;
        if (c < G8) {
            ws[q] = *(const float4*)(Wc + (size_t)c * 4);
            bs[q] = bc[c];
        } else {
            ws[q] = make_float4(0.f, 0.f, 0.f, 0.f);
            bs[q] = 0.f;
        }
    }
    __syncthreads();
    int tc = (tid & 31) * 4;     // local col group
    int tr = (tid >> 5) * 8;     // local row base
    int cg = c0 + tc;
    if (cg >= G8) return;
    float4 w0 = ws[tc], w1 = ws[tc + 1], w2 = ws[tc + 2], w3 = ws[tc + 3];
    float b0 = bs[tc], b1 = bs[tc + 1], b2 = bs[tc + 2], b3 = bs[tc + 3];
#pragma unroll
    for (int i = 0; i < 8; i++) {
        int r = r0 + tr + i;
        float4 xv = xs[tr + i];
        float4 o;
        o.x = fmaf(xv.x, w0.x, fmaf(xv.y, w0.y, fmaf(xv.z, w0.z, fmaf(xv.w, w0.w, b0))));
        o.y = fmaf(xv.x, w1.x, fmaf(xv.y, w1.y, fmaf(xv.z, w1.z, fmaf(xv.w, w1.w, b1))));
        o.z = fmaf(xv.x, w2.x, fmaf(xv.y, w2.y, fmaf(xv.z, w2.z, fmaf(xv.w, w2.w, b2))));
        o.w = fmaf(xv.x, w3.x, fmaf(xv.y, w3.y, fmaf(xv.z, w3.z, fmaf(xv.w, w3.w, b3))));
        *(float4*)(Gx + (size_t)r * G8 + cg) = o;
    }
}

// ---------------- TF32 tensor-core GEMM: C = A @ Bm^T + bias ----------------
__global__ void __launch_bounds__(256, 2)
mma_nt_kernel(int M, int N, int K,
              const float* __restrict__ A, int lda,
              const float* __restrict__ Bm, int ldb,
              const float* __restrict__ bias,
              float* __restrict__ C, int ldc) {
    __shared__ uint32_t As[2][16][132];   // [buf][k][m]
    __shared__ uint32_t Bs[2][16][132];   // [buf][k][n]
    const int tid = threadIdx.x;
    const int lane = tid & 31, warp = tid >> 5;
    const int gid = lane >> 2, qid = lane & 3;
    const int wm = (warp & 1) * 64;
    const int wn = (warp >> 1) * 32;
    const int row0 = blockIdx.y * 128, col0 = blockIdx.x * 128;

    float acc[4][4][4];
#pragma unroll
    for (int mt = 0; mt < 4; mt++)
#pragma unroll
        for (int nt = 0; nt < 4; nt++)
#pragma unroll
            for (int i = 0; i < 4; i++) acc[mt][nt][i] = 0.f;

    const int nk = (K + 15) / 16;
    float4 stA[2], stB[2];

    auto LOADG = [&](int ch) {
        int k0 = ch * 16;
#pragma unroll
        for (int i = 0; i < 2; i++) {
            int q = tid * 2 + i;
            int r = q >> 2, c = (q & 3) * 4;
            if (k0 + c + 3 < K) {
                stA[i] = *(const float4*)(A + (size_t)(row0 + r) * lda + k0 + c);
            } else {
                float tmp[4];
#pragma unroll
                for (int j = 0; j < 4; j++)
                    tmp[j] = (k0 + c + j < K)
                                 ? A[(size_t)(row0 + r) * lda + k0 + c + j] : 0.f;
                stA[i] = *(float4*)tmp;
            }
            int n = col0 + r;
            if (n < N && k0 + c + 3 < K) {
                stB[i] = *(const float4*)(Bm + (size_t)n * ldb + k0 + c);
            } else {
                float tmp[4];
#pragma unroll
                for (int j = 0; j < 4; j++)
                    tmp[j] = (n < N && k0 + c + j < K)
                                 ? Bm[(size_t)n * ldb + k0 + c + j] : 0.f;
                stB[i] = *(float4*)tmp;
            }
        }
    };

    auto STORE = [&](int buf) {
#pragma unroll
        for (int i = 0; i < 2; i++) {
            int q = tid * 2 + i;
            int r = q >> 2, c = (q & 3) * 4;
            const float* va = (const float*)&stA[i];
            const float* vb = (const float*)&stB[i];
#pragma unroll
            for (int j = 0; j < 4; j++) {
                As[buf][c + j][r] = to_tf32(va[j]);
                Bs[buf][c + j][r] = to_tf32(vb[j]);
            }
        }
    };

    auto COMPUTE = [&](int buf) {
#pragma unroll
        for (int ks = 0; ks < 2; ks++) {
            const int kb = ks * 8 + qid;
            uint32_t af[4][4], bf[4][2];
#pragma unroll
            for (int mt = 0; mt < 4; mt++) {
                int m0 = wm + mt * 16 + gid;
                af[mt][0] = As[buf][kb][m0];
                af[mt][1] = As[buf][kb][m0 + 8];
                af[mt][2] = As[buf][kb + 4][m0];
                af[mt][3] = As[buf][kb + 4][m0 + 8];
            }
#pragma unroll
            for (int nt = 0; nt < 4; nt++) {
                int n0 = wn + nt * 8 + gid;
                bf[nt][0] = Bs[buf][kb][n0];
                bf[nt][1] = Bs[buf][kb + 4][n0];
            }
#pragma unroll
            for (int mt = 0; mt < 4; mt++)
#pragma unroll
                for (int nt = 0; nt < 4; nt++) {
                    asm volatile(
                        "mma.sync.aligned.m16n8k8.row.col.f32.tf32.tf32.f32 "
                        "{%0,%1,%2,%3}, {%4,%5,%6,%7}, {%8,%9}, {%0,%1,%2,%3};"
                        : "+f"(acc[mt][nt][0]), "+f"(acc[mt][nt][1]),
                          "+f"(acc[mt][nt][2]), "+f"(acc[mt][nt][3])
                        : "r"(af[mt][0]), "r"(af[mt][1]),
                          "r"(af[mt][2]), "r"(af[mt][3]),
                          "r"(bf[nt][0]), "r"(bf[nt][1]));
                }
        }
    };

    LOADG(0);
    STORE(0);
    __syncthreads();
    for (int ch = 0; ch < nk; ch++) {
        if (ch + 1 < nk) LOADG(ch + 1);
        COMPUTE(ch & 1);
        if (ch + 1 < nk) STORE((ch + 1) & 1);
        __syncthreads();
    }

#pragma unroll
    for (int mt = 0; mt < 4; mt++) {
        int r1 = row0 + wm + mt * 16 + gid;
#pragma unroll
        for (int nt = 0; nt < 4; nt++) {
            int c0 = col0 + wn + nt * 8 + qid * 2;
            float b0 = 0.f, b1 = 0.f;
            if (bias) {
                if (c0 < N) b0 = bias[c0];
                if (c0 + 1 < N) b1 = bias[c0 + 1];
            }
            if (c0 < N) {
                C[(size_t)r1 * ldc + c0] = acc[mt][nt][0] + b0;
                C[(size_t)(r1 + 8) * ldc + c0] = acc[mt][nt][2] + b0;
            }
            if (c0 + 1 < N) {
                C[(size_t)r1 * ldc + c0 + 1] = acc[mt][nt][1] + b1;
                C[(size_t)(r1 + 8) * ldc + c0 + 1] = acc[mt][nt][3] + b1;
            }
        }
    }
}

// ------------- persistent encoder layer: all T steps in one launch ----------
__global__ void __launch_bounds__(256, 2)
enc_persist_kernel(const float* __restrict__ Gx,   // [t*B+b][G8] interleaved
                   const float* __restrict__ Wh,   // [2][G4][H]
                   float* __restrict__ h,          // [2 parity][2 dir][B][H]
                   float* __restrict__ c,
                   float* __restrict__ outseq) {   // [T][B][H2]
    const int dir = blockIdx.y;
    const int j0 = blockIdx.x * 4;
    const int tid = threadIdx.x;
    const int tx = tid & 15, ty = tid >> 4, rb = ty * 4;
    const unsigned nb = gridDim.x * gridDim.y;

    __shared__ float Wsf[16][517];
    __shared__ float As[2][12][68];
    __shared__ float gsm[64][17];

    const float* whd = Wh + (size_t)dir * G4 * H;
    for (int idx = tid; idx < 16 * H; idx += 256) {
        int r = idx / H, k = idx % H;
        int rq = r >> 2, ru = r & 3;
        Wsf[r][k] = whd[(size_t)(rq * H + j0 + ru) * H + k];
    }
    __syncthreads();

    const int SBH_ = B * H, S2_ = 2 * SBH_;
    const int eb0 = tid / 12,         ek0 = tid % 12;
    const int eb1 = (tid + 256) / 12, ek1 = (tid + 256) % 12;
    const int eb2 = (tid + 512) / 12, ek2 = (tid + 512) % 12;

    for (int s = 0; s < T; s++) {
        const int t = dir ? (T - 1 - s) : s;
        const float* hp = h + (s & 1) * S2_ + dir * SBH_;
        float* hn = h + ((s + 1) & 1) * S2_ + dir * SBH_;
        const float* cp_ = c + (s & 1) * S2_ + dir * SBH_;
        float* cn_ = c + ((s + 1) & 1) * S2_ + dir * SBH_;

        As[0][ek0][eb0] = hp[eb0 * H + ek0];
        As[0][ek1][eb1] = hp[eb1 * H + ek1];
        As[0][ek2][eb2] = hp[eb2 * H + ek2];
        __syncthreads();

        unsigned long long acc01 = 0ull, acc23 = 0ull;
        for (int kc = 0; kc < 43; kc++) {     // 516 = 43*12
            const int buf = kc & 1;
            float pf0 = 0.f, pf1 = 0.f, pf2 = 0.f;
            if (kc < 42) {
                int base = (kc + 1) * 12;
                pf0 = hp[eb0 * H + base + ek0];
                pf1 = hp[eb1 * H + base + ek1];
                pf2 = hp[eb2 * H + base + ek2];
            }
#pragma unroll
            for (int kk = 0; kk < 12; kk++) {
                const unsigned long long* h2 =
                    (const unsigned long long*)&As[buf][kk][rb];
                unsigned long long h01 = h2[0], h23 = h2[1];
                float w = Wsf[tx][kc * 12 + kk];
                unsigned long long wp = pack2(w, w);
                fma2(acc01, wp, h01);
                fma2(acc23, wp, h23);
            }
            if (kc < 42) {
                As[buf ^ 1][ek0][eb0] = pf0;
                As[buf ^ 1][ek1][eb1] = pf1;
                As[buf ^ 1][ek2][eb2] = pf2;
            }
            __syncthreads();
        }

        float a0, a1, a2, a3;
        unpack2(acc01, a0, a1);
        unpack2(acc23, a2, a3);
        gsm[rb + 0][tx] = a0; gsm[rb + 1][tx] = a1;
        gsm[rb + 2][tx] = a2; gsm[rb + 3][tx] = a3;
        __syncthreads();

        {
            int bb = tid >> 2, uu = tid & 3;
            int j = j0 + uu;
            const float* gx = Gx + ((size_t)t * B + bb) * G8 + dir * G4 + j;
            float gi = gsm[bb][uu]      + gx[0];
            float gf = gsm[bb][4 + uu]  + gx[H];
            float gg = gsm[bb][8 + uu]  + gx[2 * H];
            float go = gsm[bb][12 + uu] + gx[3 * H];
            float cp = cp_[bb * H + j];
            float si = 1.f / (1.f + expf(-gi));
            float sf = 1.f / (1.f + expf(-gf));
            float so = 1.f / (1.f + expf(-go));
            float cn = fmaf(sf, cp, si * tanhf(gg));
            float hn_ = so * tanhf(cn);
            cn_[bb * H + j] = cn;
            hn[bb * H + j] = hn_;
            outseq[((size_t)t * B + bb) * H2 + dir * H + j] = hn_;
        }
        if (s < T - 1) grid_barrier(nb);
    }
}

// ------------------------- decoder LSTM cell (1 step) -----------------------
__global__ void dec_cell_kernel(const float* __restrict__ x, int Kx,
                                const float* __restrict__ Wi,
                                const float* __restrict__ Wh,
                                const float* __restrict__ bias,
                                const float* __restrict__ hprev, float* __restrict__ hnext,
                                const float* __restrict__ cprev, float* __restrict__ cnext,
                                float* __restrict__ outcat, int outld) {
    const int dir = blockIdx.y;
    const int j0 = blockIdx.x * 4;
    const int tid = threadIdx.x;
    const int tx = tid & 15, ty = tid >> 4, rb = ty * 4;

    __shared__ float As[12][68];
    __shared__ float Ws[16][13];
    __shared__ float gsm[64][17];

    float acc0 = 0.f, acc1 = 0.f, acc2 = 0.f, acc3 = 0.f;

    for (int ph = 0; ph < 2; ph++) {
        const float* A = (ph == 0) ? x : (hprev + dir * (B * H));
        const int K = (ph == 0) ? Kx : H;
        const float* W = (ph == 0) ? (Wi + (size_t)dir * G4 * Kx)
                                   : (Wh + (size_t)dir * G4 * H);
        for (int k0 = 0; k0 < K; k0 += 12) {
            int rem = K - k0; if (rem > 12) rem = 12;
            for (int idx = tid; idx < 64 * 12; idx += 256) {
                int bb = idx / 12, kk = idx % 12;
                As[kk][bb] = (kk < rem) ? A[bb * K + k0 + kk] : 0.f;
            }
            if (tid < 192) {
                int r = tid / 12, kk = tid % 12;
                int rq = r >> 2, ru = r & 3;
                float wv = 0.f;
                if (kk < rem)
                    wv = W[(size_t)(rq * H + j0 + ru) * K + k0 + kk];
                Ws[r][kk] = wv;
            }
            __syncthreads();
#pragma unroll
            for (int kk = 0; kk < 12; kk++) {
                float4 hv = *(const float4*)&As[kk][rb];
                float w = Ws[tx][kk];
                acc0 = fmaf(hv.x, w, acc0);
                acc1 = fmaf(hv.y, w, acc1);
                acc2 = fmaf(hv.z, w, acc2);
                acc3 = fmaf(hv.w, w, acc3);
            }
            __syncthreads();
        }
    }

    gsm[rb + 0][tx] = acc0; gsm[rb + 1][tx] = acc1;
    gsm[rb + 2][tx] = acc2; gsm[rb + 3][tx] = acc3;
    __syncthreads();

    {
        int bb = tid >> 2, uu = tid & 3;
        int j = j0 + uu;
        const float* bz = bias + dir * G4;
        float gi = gsm[bb][uu]      + bz[j];
        float gf = gsm[bb][4 + uu]  + bz[H + j];
        float gg = gsm[bb][8 + uu]  + bz[2 * H + j];
        float go = gsm[bb][12 + uu] + bz[3 * H + j];
        float cp = cprev[dir * B * H + bb * H + j];
        float si = 1.f / (1.f + expf(-gi));
        float sf = 1.f / (1.f + expf(-gf));
        float so = 1.f / (1.f + expf(-go));
        float cn = fmaf(sf, cp, si * tanhf(gg));
        float hn = so * tanhf(cn);
        cnext[dir * B * H + bb * H + j] = cn;
        hnext[dir * B * H + bb * H + j] = hn;
        outcat[bb * outld + dir * H + j] = hn;
    }
}

// -------------------- skinny GEMM: C[64,N] = A@W^T (+b, tanh) ---------------
__global__ void skinny64_nt_kernel(int N, int K,
                                   const float* __restrict__ A, int lda,
                                   const float* __restrict__ W, int ldw,
                                   const float* __restrict__ bias,
                                   float* __restrict__ C, int ldc, int act) {
    __shared__ float As[16][68];
    __shared__ float Ws[16][17];
    const int tid = threadIdx.x;
    const int tx = tid & 15, ty = tid >> 4;
    const int col = blockIdx.x * 16 + tx;

    float acc[4] = {0.f, 0.f, 0.f, 0.f};

    for (int k0 = 0; k0 < K; k0 += 16) {
        for (int idx = tid; idx < 64 * 16; idx += 256) {
            int r = idx >> 4, kk = idx & 15;
            As[kk][r] = (k0 + kk < K) ? A[(size_t)r * lda + k0 + kk] : 0.f;
        }
        {
            int cix = tid & 15, kk = tid >> 4;
            int cg = blockIdx.x * 16 + cix;
            float wv = 0.f;
            if (cg < N && (k0 + kk) < K)
                wv = W[(size_t)cg * ldw + k0 + kk];
            Ws[cix][kk] = wv;
        }
        __syncthreads();
#pragma unroll
        for (int kk = 0; kk < 16; kk++) {
            float w = Ws[tx][kk];
            float4 a = *(const float4*)&As[kk][ty * 4];
            acc[0] = fmaf(a.x, w, acc[0]);
            acc[1] = fmaf(a.y, w, acc[1]);
            acc[2] = fmaf(a.z, w, acc[2]);
            acc[3] = fmaf(a.w, w, acc[3]);
        }
        __syncthreads();
    }

    if (col < N) {
#pragma unroll
        for (int i = 0; i < 4; i++) {
            int r = ty * 4 + i;
            float v = acc[i];
            if (bias) v += bias[col];
            if (act) v = tanhf(v);
            C[(size_t)r * ldc + col] = v;
        }
    }
}

// ------------------------------ attention ----------------------------------
// score[b*T+t] = sum_h v[h]*tanh_approx(E2[(t*B+b)*H2+h] + dbuf[b*H2+h])
__global__ void score_kernel(const float* __restrict__ E2,
                             const float* __restrict__ dbuf,
                             const float* __restrict__ v,
                             float* __restrict__ score) {
    int w = blockIdx.x * 8 + (threadIdx.x >> 5);
    int lane = threadIdx.x & 31;
    int bb = w & 63, t = w >> 6;
    const float4* e = (const float4*)(E2 + (size_t)w * H2);
    const float4* d = (const float4*)(dbuf + (size_t)bb * H2);
    const float4* vv = (const float4*)v;
    float s = 0.f;
    for (int q = lane; q < H2 / 4; q += 32) {   // 258 float4 groups
        float4 ev = e[q], dv = d[q], vq = vv[q];
        s = fmaf(vq.x, ftanh(ev.x + dv.x), s);
        s = fmaf(vq.y, ftanh(ev.y + dv.y), s);
        s = fmaf(vq.z, ftanh(ev.z + dv.z), s);
        s = fmaf(vq.w, ftanh(ev.w + dv.w), s);
    }
#pragma unroll
    for (int o = 16; o > 0; o >>= 1)
        s += __shfl_down_sync(0xffffffffu, s, o);
    if (lane == 0) score[bb * T + t] = s;
}

// fused softmax over T + context accumulation. block = b, 512 threads.
__global__ void attn_kernel(const float* __restrict__ score,
                            const float* __restrict__ enc,
                            float* __restrict__ cc) {
    __shared__ float sm[T];
    __shared__ float aws[T];
    int bb = blockIdx.x, tid = threadIdx.x;
    float v = score[bb * T + tid];
    sm[tid] = v;
    __syncthreads();
    for (int st = 256; st > 0; st >>= 1) {
        if (tid < st) sm[tid] = fmaxf(sm[tid], sm[tid + st]);
        __syncthreads();
    }
    float mx = sm[0];
    __syncthreads();
    float e = expf(v - mx);
    sm[tid] = e;
    __syncthreads();
    for (int st = 256; st > 0; st >>= 1) {
        if (tid < st) sm[tid] += sm[tid + st];
        __syncthreads();
    }
    aws[tid] = e / sm[0];
    __syncthreads();

    float acc[3] = {0.f, 0.f, 0.f};
    for (int t = 0; t < T; t++) {
        float wt = aws[t];
        const float* ep = enc + ((size_t)t * B + bb) * H2;
#pragma unroll
        for (int j = 0; j < 3; j++) {
            int hh = tid + j * 512;
            if (hh < H2) acc[j] = fmaf(wt, ep[hh], acc[j]);
        }
    }
#pragma unroll
    for (int j = 0; j < 3; j++) {
        int hh = tid + j * 512;
        if (hh < H2) cc[bb * (2 * H2) + H2 + hh] = acc[j];
    }
}

// -------------- fused logits + cross-entropy (single block, det.) -----------
__global__ void ce_fused_kernel(const float* __restrict__ co,
                                const float* __restrict__ out_W,
                                const float* __restrict__ out_b,
                                const int* __restrict__ lab,
                                float* __restrict__ loss) {
    __shared__ float lg[64][20];
    __shared__ float red[64];
    int tid = threadIdx.x;           // 1024 threads
    int bb = tid >> 4, slot = tid & 15;
    for (int cix = slot; cix < SEQ; cix += 16) {
        const float* a = co + bb * H2;
        const float* w = out_W + cix * H2;
        float s = out_b[cix];
#pragma unroll 4
        for (int k = 0; k < H2; k++) s = fmaf(a[k], w[k], s);
        lg[bb][cix] = s;
    }
    __syncthreads();
    if (slot == 0) {
        float m = lg[bb][0];
#pragma unroll
        for (int i = 1; i < SEQ; i++) m = fmaxf(m, lg[bb][i]);
        float s = 0.f;
#pragma unroll
        for (int i = 0; i < SEQ; i++) s += expf(lg[bb][i] - m);
        red[bb] = -(lg[bb][lab[bb]] - m - logf(s));
    }
    __syncthreads();
    if (tid == 0) {
        float tot = 0.f;
        for (int i = 0; i < 64; i++) tot += red[i];
        loss[0] += tot / 64.f;
    }
}

// ------------------------------- host --------------------------------------
static float* symaddr(const void* devsym) {
    void* p = nullptr;
    cudaGetSymbolAddress(&p, devsym);
    return (float*)p;
}

extern "C" void kernel_launch(void* const* d_in, const int* in_sizes, int n_in,
                              void* d_out, int out_size) {
    (void)in_sizes; (void)n_in; (void)out_size;
    const float* x        = (const float*)d_in[0];
    const float* y        = (const float*)d_in[1];
    const int*   label    = (const int*)d_in[2];
    const float* expand_W = (const float*)d_in[3];
    const float* expand_b = (const float*)d_in[4];
    const float* eWi0     = (const float*)d_in[5];
    const float* eWh0     = (const float*)d_in[6];
    const float* eb0      = (const float*)d_in[7];
    const float* eWi1     = (const float*)d_in[8];
    const float* eWh1     = (const float*)d_in[9];
    const float* eb1      = (const float*)d_in[10];
    const float* dWi0     = (const float*)d_in[11];
    const float* dWh0     = (const float*)d_in[12];
    const float* db0      = (const float*)d_in[13];
    const float* dWi1     = (const float*)d_in[14];
    const float* dWh1     = (const float*)d_in[15];
    const float* db1      = (const float*)d_in[16];
    const float* attn_W   = (const float*)d_in[17];
    const float* attn_b   = (const float*)d_in[18];
    const float* attn_v   = (const float*)d_in[19];
    const float* concat_W = (const float*)d_in[20];
    const float* concat_b = (const float*)d_in[21];
    const float* out_W    = (const float*)d_in[22];
    const float* out_b    = (const float*)d_in[23];

    float* Gx     = symaddr(&g_Gx);
    float* out0   = symaddr(&g_out0);
    float* outenc = symaddr(&g_outenc);
    float* E2     = symaddr(&g_E2);
    float* Wc     = symaddr(&g_Wc);
    float* bc     = symaddr(&g_bc);
    float* eh     = symaddr(&g_eh);
    float* ec     = symaddr(&g_ec);
    float* dh     = symaddr(&g_dh);
    float* dc     = symaddr(&g_dc);
    float* l0     = symaddr(&g_l0);
    float* cc     = symaddr(&g_cc);
    float* dbuf   = symaddr(&g_dbuf);
    float* co     = symaddr(&g_co);
    float* score  = symaddr(&g_score);
    float* loss   = symaddr(&g_loss);

    const int SBH = B * H;
    const int S2  = 2 * SBH;
    const int S4  = 4 * SBH;

    zero_kernel<<<1, 32>>>(loss, 1);
    zero_kernel<<<(S2 + 255) / 256, 256>>>(eh, S2);
    zero_kernel<<<(S2 + 255) / 256, 256>>>(ec, S2);

    // ---- encoder layer 0: fold expand into Wi, then K=4 "GEMM" ----
    fold0_kernel<<<(G8 + 127) / 128, 128>>>(eWi0, expand_W, expand_b, eb0, Wc, bc);
    gx0_kernel<<<dim3(33, TB / 64), 256>>>(x, Wc, bc, Gx);
    enc_persist_kernel<<<dim3(129, 2), 256>>>(Gx, eWh0, eh, ec, out0);
    copy2_kernel<<<(S2 + 255) / 256, 256>>>(eh, ec, dh, dc, S2);

    // ---- encoder layer 1 ----
    zero_kernel<<<(S2 + 255) / 256, 256>>>(eh, S2);
    zero_kernel<<<(S2 + 255) / 256, 256>>>(ec, S2);
    mma_nt_kernel<<<dim3((G8 + 127) / 128, TB / 128), 256>>>(
        TB, G8, H2, out0, H2, eWi1, H2, eb1, Gx, G8);
    enc_persist_kernel<<<dim3(129, 2), 256>>>(Gx, eWh1, eh, ec, outenc);
    copy2_kernel<<<(S2 + 255) / 256, 256>>>(eh, ec, dh + S2, dc + S2, S2);

    // ---- attention precompute: E2 = outenc @ attn_W[:,1032:]^T + attn_b ----
    mma_nt_kernel<<<dim3((H2 + 127) / 128, TB / 128), 256>>>(
        TB, H2, H2, outenc, H2, attn_W + H2, G4, attn_b, E2, H2);

    // ---- decoder loop ----
    for (int ts = 0; ts < NY; ts++) {
        int pp = (ts & 1) * S4, np = ((ts + 1) & 1) * S4;
        dec_cell_kernel<<<dim3(129, 2), 256>>>(
            y + (size_t)ts * B * SEQ, SEQ, dWi0, dWh0, db0,
            dh + pp, dh + np, dc + pp, dc + np, l0, H2);
        dec_cell_kernel<<<dim3(129, 2), 256>>>(
            l0, H2, dWi1, dWh1, db1,
            dh + pp + S2, dh + np + S2, dc + pp + S2, dc + np + S2,
            cc, 2 * H2);
        skinny64_nt_kernel<<<(H2 + 15) / 16, 256>>>(
            H2, H2, cc, 2 * H2, attn_W, G4, nullptr, dbuf, H2, 0);
        score_kernel<<<TB / 8, 256>>>(E2, dbuf, attn_v, score);
        attn_kernel<<<B, 512>>>(score, outenc, cc);
        skinny64_nt_kernel<<<(H2 + 15) / 16, 256>>>(
            H2, G4, cc, 2 * H2, concat_W, G4, concat_b, co, H2, 1);
        ce_fused_kernel<<<1, 1024>>>(co, out_W, out_b, label + ts * B, loss);
    }

    write_out_kernel<<<1, 1>>>((float*)d_out, loss);
}

// round 13
// speedup vs baseline: 1.1175x; 1.1175x over previous
#include <cuda_runtime.h>
#include <math.h>
#include <stdint.h>

#define H   516
#define T   512
#define B   64
#define NY  20
#define SEQ 20
#define G4  2064
#define H2  1032
#define TB  32768
#define G8  4128
#define BH  33024
#define NBLK 148

// enc smem carve (floats)
#define OFF_W  0
#define SZ_W   (32 * 517)
#define OFF_H  (OFF_W + SZ_W)
#define SZ_H   (516 * 64)
#define OFF_G  (OFF_H + SZ_H)
#define SZ_G   (2 * 64 * 33)
#define ENC_SMEM_BYTES ((OFF_G + SZ_G) * 4)

typedef unsigned long long ULL;

__device__ float g_Gx[TB * G8];
__device__ float g_out0[TB * H2];
__device__ float g_outenc[TB * H2];
__device__ float g_E2[TB * H2];
__device__ float g_Wc[G8 * 4];
__device__ float g_bc[G8];
__device__ float g_hT[2 * 2 * 516 * 64];    // [parity][dir][k][b]
__device__ float g_dh[2 * 4 * BH];
__device__ float g_dc[2 * 4 * BH];
__device__ float g_l0[B * H2];
__device__ float g_cc[B * 2 * H2];
__device__ float g_dbuf[B * H2];
__device__ float g_co[B * H2];
__device__ float g_score[B * T];
__device__ float g_loss[1];
__device__ unsigned g_bar[NBLK * 32 + 32];

__device__ __forceinline__ void fma2(ULL& d, ULL a, ULL b) {
    asm("fma.rn.f32x2 %0, %1, %2, %0;" : "+l"(d) : "l"(a), "l"(b));
}
__device__ __forceinline__ ULL pack2(float lo, float hi) {
    ULL r; asm("mov.b64 %0, {%1, %2};" : "=l"(r) : "f"(lo), "f"(hi)); return r;
}
__device__ __forceinline__ void unpack2(ULL v, float& lo, float& hi) {
    asm("mov.b64 {%0, %1}, %2;" : "=f"(lo), "=f"(hi) : "l"(v));
}
__device__ __forceinline__ uint32_t to_tf32(float x) {
    uint32_t r; asm("cvt.rna.tf32.f32 %0, %1;" : "=r"(r) : "f"(x)); return r;
}
__device__ __forceinline__ float ftanh(float x) {
    float r; asm("tanh.approx.f32 %0, %1;" : "=f"(r) : "f"(x)); return r;
}

// contention-free grid barrier: slot per block (128B apart), block0 aggregates
__device__ __forceinline__ void gbar(int bid, int tid, unsigned target) {
    __syncthreads();
    if (bid == 0) {
        if (tid >= 1 && tid < NBLK) {
            while (*(volatile unsigned*)&g_bar[tid * 32] < target) __nanosleep(40);
        }
        __syncthreads();
        if (tid == 0) {
            __threadfence();
            *(volatile unsigned*)&g_bar[NBLK * 32] = target;
        }
        __syncthreads();
    } else {
        if (tid == 0) {
            __threadfence();
            *(volatile unsigned*)&g_bar[bid * 32] = target;
            while (*(volatile unsigned*)&g_bar[NBLK * 32] < target) __nanosleep(40);
            __threadfence();
        }
        __syncthreads();
    }
}

__global__ void zero_kernel(float* p, int n) {
    int i = blockIdx.x * 256 + threadIdx.x;
    if (i < n) p[i] = 0.f;
}
__global__ void write_out_kernel(float* out, const float* loss) { out[0] = loss[0]; }

__global__ void fold0_kernel(const float* __restrict__ eWi0, const float* __restrict__ We,
                             const float* __restrict__ be, const float* __restrict__ eb0,
                             float* __restrict__ Wc, float* __restrict__ bc) {
    int i = blockIdx.x * 128 + threadIdx.x;
    if (i >= G8) return;
    const float* wi = eWi0 + (size_t)i * 256;
    float a0 = 0.f, a1 = 0.f, a2 = 0.f, a3 = 0.f, ab = eb0[i];
    for (int k = 0; k < 256; k++) {
        float w = wi[k];
        float4 we4 = *(const float4*)(We + k * 4);
        a0 = fmaf(w, we4.x, a0); a1 = fmaf(w, we4.y, a1);
        a2 = fmaf(w, we4.z, a2); a3 = fmaf(w, we4.w, a3);
        ab = fmaf(w, be[k], ab);
    }
    *(float4*)(Wc + (size_t)i * 4) = make_float4(a0, a1, a2, a3);
    bc[i] = ab;
}

__global__ void gx0_kernel(const float* __restrict__ x, const float* __restrict__ Wc,
                           const float* __restrict__ bc, float* __restrict__ Gx) {
    __shared__ float4 xs[64];
    __shared__ float4 ws[128];
    __shared__ float bs[128];
    int tid = threadIdx.x;
    int r0 = blockIdx.y * 64, c0 = blockIdx.x * 128;
    if (tid < 64) xs[tid] = *(const float4*)(x + (size_t)(r0 + tid) * 4);
    if (tid >= 128) {
        int q = tid - 128; int c = c0 + q;
        if (c < G8) { ws[q] = *(const float4*)(Wc + (size_t)c * 4); bs[q] = bc[c]; }
        else { ws[q] = make_float4(0.f, 0.f, 0.f, 0.f); bs[q] = 0.f; }
    }
    __syncthreads();
    int tc = (tid & 31) * 4, tr = (tid >> 5) * 8;
    int cg = c0 + tc;
    if (cg >= G8) return;
    float4 w0 = ws[tc], w1 = ws[tc + 1], w2 = ws[tc + 2], w3 = ws[tc + 3];
    float b0 = bs[tc], b1 = bs[tc + 1], b2 = bs[tc + 2], b3 = bs[tc + 3];
#pragma unroll
    for (int i = 0; i < 8; i++) {
        int r = r0 + tr + i;
        float4 xv = xs[tr + i];
        float4 o;
        o.x = fmaf(xv.x, w0.x, fmaf(xv.y, w0.y, fmaf(xv.z, w0.z, fmaf(xv.w, w0.w, b0))));
        o.y = fmaf(xv.x, w1.x, fmaf(xv.y, w1.y, fmaf(xv.z, w1.z, fmaf(xv.w, w1.w, b1))));
        o.z = fmaf(xv.x, w2.x, fmaf(xv.y, w2.y, fmaf(xv.z, w2.z, fmaf(xv.w, w2.w, b2))));
        o.w = fmaf(xv.x, w3.x, fmaf(xv.y, w3.y, fmaf(xv.z, w3.z, fmaf(xv.w, w3.w, b3))));
        *(float4*)(Gx + (size_t)r * G8 + cg) = o;
    }
}

// TF32 MMA GEMM: C = A @ Bm^T + bias
__global__ void __launch_bounds__(256, 2)
mma_nt_kernel(int M, int N, int K,
              const float* __restrict__ A, int lda,
              const float* __restrict__ Bm, int ldb,
              const float* __restrict__ bias,
              float* __restrict__ C, int ldc) {
    __shared__ uint32_t As[2][16][132];
    __shared__ uint32_t Bs[2][16][132];
    const int tid = threadIdx.x;
    const int lane = tid & 31, warp = tid >> 5;
    const int gid = lane >> 2, qid = lane & 3;
    const int wm = (warp & 1) * 64, wn = (warp >> 1) * 32;
    const int row0 = blockIdx.y * 128, col0 = blockIdx.x * 128;

    float acc[4][4][4];
#pragma unroll
    for (int mt = 0; mt < 4; mt++)
#pragma unroll
        for (int nt = 0; nt < 4; nt++)
#pragma unroll
            for (int i = 0; i < 4; i++) acc[mt][nt][i] = 0.f;

    const int nk = (K + 15) / 16;
    float4 stA[2], stB[2];

    auto LOADG = [&](int ch) {
        int k0 = ch * 16;
#pragma unroll
        for (int i = 0; i < 2; i++) {
            int q = tid * 2 + i;
            int r = q >> 2, c = (q & 3) * 4;
            if (k0 + c + 3 < K) {
                stA[i] = *(const float4*)(A + (size_t)(row0 + r) * lda + k0 + c);
            } else {
                float tmp[4];
#pragma unroll
                for (int j = 0; j < 4; j++)
                    tmp[j] = (k0 + c + j < K) ? A[(size_t)(row0 + r) * lda + k0 + c + j] : 0.f;
                stA[i] = *(float4*)tmp;
            }
            int n = col0 + r;
            if (n < N && k0 + c + 3 < K) {
                stB[i] = *(const float4*)(Bm + (size_t)n * ldb + k0 + c);
            } else {
                float tmp[4];
#pragma unroll
                for (int j = 0; j < 4; j++)
                    tmp[j] = (n < N && k0 + c + j < K) ? Bm[(size_t)n * ldb + k0 + c + j] : 0.f;
                stB[i] = *(float4*)tmp;
            }
        }
    };
    auto STORE = [&](int buf) {
#pragma unroll
        for (int i = 0; i < 2; i++) {
            int q = tid * 2 + i;
            int r = q >> 2, c = (q & 3) * 4;
            const float* va = (const float*)&stA[i];
            const float* vb = (const float*)&stB[i];
#pragma unroll
            for (int j = 0; j < 4; j++) {
                As[buf][c + j][r] = to_tf32(va[j]);
                Bs[buf][c + j][r] = to_tf32(vb[j]);
            }
        }
    };
    auto COMPUTE = [&](int buf) {
#pragma unroll
        for (int ks = 0; ks < 2; ks++) {
            const int kb = ks * 8 + qid;
            uint32_t af[4][4], bf[4][2];
#pragma unroll
            for (int mt = 0; mt < 4; mt++) {
                int m0 = wm + mt * 16 + gid;
                af[mt][0] = As[buf][kb][m0];     af[mt][1] = As[buf][kb][m0 + 8];
                af[mt][2] = As[buf][kb + 4][m0]; af[mt][3] = As[buf][kb + 4][m0 + 8];
            }
#pragma unroll
            for (int nt = 0; nt < 4; nt++) {
                int n0 = wn + nt * 8 + gid;
                bf[nt][0] = Bs[buf][kb][n0]; bf[nt][1] = Bs[buf][kb + 4][n0];
            }
#pragma unroll
            for (int mt = 0; mt < 4; mt++)
#pragma unroll
                for (int nt = 0; nt < 4; nt++) {
                    asm volatile(
                        "mma.sync.aligned.m16n8k8.row.col.f32.tf32.tf32.f32 "
                        "{%0,%1,%2,%3}, {%4,%5,%6,%7}, {%8,%9}, {%0,%1,%2,%3};"
                        : "+f"(acc[mt][nt][0]), "+f"(acc[mt][nt][1]),
                          "+f"(acc[mt][nt][2]), "+f"(acc[mt][nt][3])
                        : "r"(af[mt][0]), "r"(af[mt][1]),
                          "r"(af[mt][2]), "r"(af[mt][3]),
                          "r"(bf[nt][0]), "r"(bf[nt][1]));
                }
        }
    };

    LOADG(0); STORE(0); __syncthreads();
    for (int ch = 0; ch < nk; ch++) {
        if (ch + 1 < nk) LOADG(ch + 1);
        COMPUTE(ch & 1);
        if (ch + 1 < nk) STORE((ch + 1) & 1);
        __syncthreads();
    }
#pragma unroll
    for (int mt = 0; mt < 4; mt++) {
        int r1 = row0 + wm + mt * 16 + gid;
#pragma unroll
        for (int nt = 0; nt < 4; nt++) {
            int c0 = col0 + wn + nt * 8 + qid * 2;
            float b0 = 0.f, b1 = 0.f;
            if (bias) {
                if (c0 < N) b0 = bias[c0];
                if (c0 + 1 < N) b1 = bias[c0 + 1];
            }
            if (c0 < N) {
                C[(size_t)r1 * ldc + c0] = acc[mt][nt][0] + b0;
                C[(size_t)(r1 + 8) * ldc + c0] = acc[mt][nt][2] + b0;
            }
            if (c0 + 1 < N) {
                C[(size_t)r1 * ldc + c0 + 1] = acc[mt][nt][1] + b1;
                C[(size_t)(r1 + 8) * ldc + c0 + 1] = acc[mt][nt][3] + b1;
            }
        }
    }
}

// persistent encoder layer v2: grid (74, 2), 512 thr, 1 block/SM, c in regs
__global__ void __launch_bounds__(512, 1)
enc_persist2(const float* __restrict__ Gx,   // [t*B+b][G8]
             const float* __restrict__ Wh,   // [2][G4][H]
             float* __restrict__ hT,         // [2][2][516][64]
             float* __restrict__ outseq,     // [T][B][H2]
             float* __restrict__ dh_fin,     // [2 dir][B][H]
             float* __restrict__ dc_fin) {
    extern __shared__ float smem[];
    float* Wsf = smem + OFF_W;   // [32][517] row = g*8+jj
    float* hTs = smem + OFF_H;   // [516][64]
    float* gsm = smem + OFF_G;   // [2][64][33]

    const int dir = blockIdx.y, bx = blockIdx.x;
    const int bid = dir * 74 + bx;
    const int j0 = bx * 7;
    const int tid = threadIdx.x;

    // GEMM mapping: warp -> (bg, ks); lane -> row
    const int warp = tid >> 5, lane = tid & 31;
    const int bg = warp >> 1, ks = warp & 1;
    const int b0 = bg * 8;
    float* wrow = Wsf + lane * 517 + ks * 258;

    // cell mapping
    const int cb = tid & 63, cjj = tid >> 6;   // cjj 0..7
    const int cj = j0 + cjj;
    const bool cell_act = (cjj < 7) && (cj < H);

    // load weights once (padded rows zero)
    const float* whd = Wh + (size_t)dir * G4 * H;
    for (int idx = tid; idx < 32 * 517; idx += 512) {
        int r = idx / 517, k = idx - r * 517;
        int g = r >> 3, jj = r & 7;
        float wv = 0.f;
        if (jj < 7 && (j0 + jj) < H && k < H)
            wv = whd[(size_t)(g * H + j0 + jj) * H + k];
        Wsf[idx] = wv;
    }
    __syncthreads();

    float creg = 0.f;

    for (int s = 0; s < T; s++) {
        const int t = dir ? (T - 1 - s) : s;
        const int rp = s & 1, wp = (s + 1) & 1;

        // prefetch gate inputs (independent of h)
        float gxi = 0.f, gxf = 0.f, gxg = 0.f, gxo = 0.f;
        if (cell_act) {
            const float* gx = Gx + ((size_t)t * B + cb) * G8 + dir * G4 + cj;
            gxi = gx[0]; gxf = gx[H]; gxg = gx[2 * H]; gxo = gx[3 * H];
        }

        // stage h^T (132KB)
        {
            const float4* src = (const float4*)(hT + ((size_t)rp * 2 + dir) * (516 * 64));
            float4* dst = (float4*)hTs;
            for (int idx = tid; idx < (516 * 64) / 4; idx += 512) dst[idx] = src[idx];
        }
        __syncthreads();

        // GEMM: row=lane, 8 batches, half-K
        ULL a0 = 0ull, a1 = 0ull, a2 = 0ull, a3 = 0ull;
        {
            const float* hb = hTs + (size_t)(ks * 258) * 64 + b0;
#pragma unroll 2
            for (int k = 0; k < 258; k++) {
                float w = wrow[k];
                ULL wpk = pack2(w, w);
                longlong2 v0 = *(const longlong2*)(hb);
                longlong2 v1 = *(const longlong2*)(hb + 4);
                fma2(a0, wpk, (ULL)v0.x);
                fma2(a1, wpk, (ULL)v0.y);
                fma2(a2, wpk, (ULL)v1.x);
                fma2(a3, wpk, (ULL)v1.y);
                hb += 64;
            }
        }
        {
            float v0, v1;
            float* g = gsm + (size_t)(ks * 64 + b0) * 33 + lane;
            unpack2(a0, v0, v1); g[0] = v0;   g[33] = v1;
            unpack2(a1, v0, v1); g[66] = v0;  g[99] = v1;
            unpack2(a2, v0, v1); g[132] = v0; g[165] = v1;
            unpack2(a3, v0, v1); g[198] = v0; g[231] = v1;
        }
        __syncthreads();

        // cell
        if (cell_act) {
            const float* ga = gsm + (size_t)cb * 33;
            const float* gb = gsm + (size_t)(64 + cb) * 33;
            float gi = ga[cjj]      + gb[cjj]      + gxi;
            float gf = ga[8 + cjj]  + gb[8 + cjj]  + gxf;
            float gg = ga[16 + cjj] + gb[16 + cjj] + gxg;
            float go = ga[24 + cjj] + gb[24 + cjj] + gxo;
            float si = 1.f / (1.f + expf(-gi));
            float sf = 1.f / (1.f + expf(-gf));
            float so = 1.f / (1.f + expf(-go));
            float cn = fmaf(sf, creg, si * tanhf(gg));
            float hn = so * tanhf(cn);
            creg = cn;
            hT[((size_t)wp * 2 + dir) * (516 * 64) + (size_t)cj * 64 + cb] = hn;
            outseq[((size_t)t * B + cb) * H2 + dir * H + cj] = hn;
            if (s == T - 1) {
                dh_fin[dir * BH + cb * H + cj] = hn;
                dc_fin[dir * BH + cb * H + cj] = cn;
            }
        }

        if (s < T - 1) gbar(bid, tid, (unsigned)(s + 1));
    }
}

__global__ void dec_cell_kernel(const float* __restrict__ x, int Kx,
                                const float* __restrict__ Wi, const float* __restrict__ Wh,
                                const float* __restrict__ bias,
                                const float* __restrict__ hprev, float* __restrict__ hnext,
                                const float* __restrict__ cprev, float* __restrict__ cnext,
                                float* __restrict__ outcat, int outld) {
    const int dir = blockIdx.y;
    const int j0 = blockIdx.x * 4;
    const int tid = threadIdx.x;
    const int tx = tid & 15, ty = tid >> 4, rb = ty * 4;

    __shared__ float As[12][68];
    __shared__ float Ws[16][13];
    __shared__ float gsm[64][17];

    float acc0 = 0.f, acc1 = 0.f, acc2 = 0.f, acc3 = 0.f;

    for (int ph = 0; ph < 2; ph++) {
        const float* A = (ph == 0) ? x : (hprev + dir * BH);
        const int K = (ph == 0) ? Kx : H;
        const float* W = (ph == 0) ? (Wi + (size_t)dir * G4 * Kx) : (Wh + (size_t)dir * G4 * H);
        for (int k0 = 0; k0 < K; k0 += 12) {
            int rem = K - k0; if (rem > 12) rem = 12;
            for (int idx = tid; idx < 64 * 12; idx += 256) {
                int bb = idx / 12, kk = idx % 12;
                As[kk][bb] = (kk < rem) ? A[bb * K + k0 + kk] : 0.f;
            }
            if (tid < 192) {
                int r = tid / 12, kk = tid % 12;
                int rq = r >> 2, ru = r & 3;
                float wv = 0.f;
                if (kk < rem) wv = W[(size_t)(rq * H + j0 + ru) * K + k0 + kk];
                Ws[r][kk] = wv;
            }
            __syncthreads();
#pragma unroll
            for (int kk = 0; kk < 12; kk++) {
                float4 hv = *(const float4*)&As[kk][rb];
                float w = Ws[tx][kk];
                acc0 = fmaf(hv.x, w, acc0);
                acc1 = fmaf(hv.y, w, acc1);
                acc2 = fmaf(hv.z, w, acc2);
                acc3 = fmaf(hv.w, w, acc3);
            }
            __syncthreads();
        }
    }
    gsm[rb + 0][tx] = acc0; gsm[rb + 1][tx] = acc1;
    gsm[rb + 2][tx] = acc2; gsm[rb + 3][tx] = acc3;
    __syncthreads();
    {
        int bb = tid >> 2, uu = tid & 3;
        int j = j0 + uu;
        const float* bz = bias + dir * G4;
        float gi = gsm[bb][uu]      + bz[j];
        float gf = gsm[bb][4 + uu]  + bz[H + j];
        float gg = gsm[bb][8 + uu]  + bz[2 * H + j];
        float go = gsm[bb][12 + uu] + bz[3 * H + j];
        float cp = cprev[dir * BH + bb * H + j];
        float si = 1.f / (1.f + expf(-gi));
        float sf = 1.f / (1.f + expf(-gf));
        float so = 1.f / (1.f + expf(-go));
        float cn = fmaf(sf, cp, si * tanhf(gg));
        float hn = so * tanhf(cn);
        cnext[dir * BH + bb * H + j] = cn;
        hnext[dir * BH + bb * H + j] = hn;
        outcat[bb * outld + dir * H + j] = hn;
    }
}

__global__ void skinny64_nt_kernel(int N, int K,
                                   const float* __restrict__ A, int lda,
                                   const float* __restrict__ W, int ldw,
                                   const float* __restrict__ bias,
                                   float* __restrict__ C, int ldc, int act) {
    __shared__ float As[16][68];
    __shared__ float Ws[16][17];
    const int tid = threadIdx.x;
    const int tx = tid & 15, ty = tid >> 4;
    const int col = blockIdx.x * 16 + tx;
    float acc[4] = {0.f, 0.f, 0.f, 0.f};
    for (int k0 = 0; k0 < K; k0 += 16) {
        for (int idx = tid; idx < 64 * 16; idx += 256) {
            int r = idx >> 4, kk = idx & 15;
            As[kk][r] = (k0 + kk < K) ? A[(size_t)r * lda + k0 + kk] : 0.f;
        }
        {
            int cix = tid & 15, kk = tid >> 4;
            int cg = blockIdx.x * 16 + cix;
            float wv = 0.f;
            if (cg < N && (k0 + kk) < K) wv = W[(size_t)cg * ldw + k0 + kk];
            Ws[cix][kk] = wv;
        }
        __syncthreads();
#pragma unroll
        for (int kk = 0; kk < 16; kk++) {
            float w = Ws[tx][kk];
            float4 a = *(const float4*)&As[kk][ty * 4];
            acc[0] = fmaf(a.x, w, acc[0]);
            acc[1] = fmaf(a.y, w, acc[1]);
            acc[2] = fmaf(a.z, w, acc[2]);
            acc[3] = fmaf(a.w, w, acc[3]);
        }
        __syncthreads();
    }
    if (col < N) {
#pragma unroll
        for (int i = 0; i < 4; i++) {
            int r = ty * 4 + i;
            float v = acc[i];
            if (bias) v += bias[col];
            if (act) v = tanhf(v);
            C[(size_t)r * ldc + col] = v;
        }
    }
}

__global__ void score_kernel(const float* __restrict__ E2, const float* __restrict__ dbuf,
                             const float* __restrict__ v, float* __restrict__ score) {
    int w = blockIdx.x * 8 + (threadIdx.x >> 5);
    int lane = threadIdx.x & 31;
    int bb = w & 63, t = w >> 6;
    const float4* e = (const float4*)(E2 + (size_t)w * H2);
    const float4* d = (const float4*)(dbuf + (size_t)bb * H2);
    const float4* vv = (const float4*)v;
    float s = 0.f;
    for (int q = lane; q < H2 / 4; q += 32) {
        float4 ev = e[q], dv = d[q], vq = vv[q];
        s = fmaf(vq.x, ftanh(ev.x + dv.x), s);
        s = fmaf(vq.y, ftanh(ev.y + dv.y), s);
        s = fmaf(vq.z, ftanh(ev.z + dv.z), s);
        s = fmaf(vq.w, ftanh(ev.w + dv.w), s);
    }
#pragma unroll
    for (int o = 16; o > 0; o >>= 1) s += __shfl_down_sync(0xffffffffu, s, o);
    if (lane == 0) score[bb * T + t] = s;
}

__global__ void attn_kernel(const float* __restrict__ score, const float* __restrict__ enc,
                            float* __restrict__ cc) {
    __shared__ float sm[T];
    __shared__ float aws[T];
    int bb = blockIdx.x, tid = threadIdx.x;
    float v = score[bb * T + tid];
    sm[tid] = v;
    __syncthreads();
    for (int st = 256; st > 0; st >>= 1) {
        if (tid < st) sm[tid] = fmaxf(sm[tid], sm[tid + st]);
        __syncthreads();
    }
    float mx = sm[0];
    __syncthreads();
    float e = expf(v - mx);
    sm[tid] = e;
    __syncthreads();
    for (int st = 256; st > 0; st >>= 1) {
        if (tid < st) sm[tid] += sm[tid + st];
        __syncthreads();
    }
    aws[tid] = e / sm[0];
    __syncthreads();
    float acc[3] = {0.f, 0.f, 0.f};
    for (int t = 0; t < T; t++) {
        float wt = aws[t];
        const float* ep = enc + ((size_t)t * B + bb) * H2;
#pragma unroll
        for (int j = 0; j < 3; j++) {
            int hh = tid + j * 512;
            if (hh < H2) acc[j] = fmaf(wt, ep[hh], acc[j]);
        }
    }
#pragma unroll
    for (int j = 0; j < 3; j++) {
        int hh = tid + j * 512;
        if (hh < H2) cc[bb * (2 * H2) + H2 + hh] = acc[j];
    }
}

__global__ void ce_fused_kernel(const float* __restrict__ co, const float* __restrict__ out_W,
                                const float* __restrict__ out_b, const int* __restrict__ lab,
                                float* __restrict__ loss) {
    __shared__ float lg[64][20];
    __shared__ float red[64];
    int tid = threadIdx.x;
    int bb = tid >> 4, slot = tid & 15;
    for (int cix = slot; cix < SEQ; cix += 16) {
        const float* a = co + bb * H2;
        const float* w = out_W + cix * H2;
        float s = out_b[cix];
#pragma unroll 4
        for (int k = 0; k < H2; k++) s = fmaf(a[k], w[k], s);
        lg[bb][cix] = s;
    }
    __syncthreads();
    if (slot == 0) {
        float m = lg[bb][0];
#pragma unroll
        for (int i = 1; i < SEQ; i++) m = fmaxf(m, lg[bb][i]);
        float s = 0.f;
#pragma unroll
        for (int i = 0; i < SEQ; i++) s += expf(lg[bb][i] - m);
        red[bb] = -(lg[bb][lab[bb]] - m - logf(s));
    }
    __syncthreads();
    if (tid == 0) {
        float tot = 0.f;
        for (int i = 0; i < 64; i++) tot += red[i];
        loss[0] += tot / 64.f;
    }
}

static float* symaddr(const void* devsym) {
    void* p = nullptr;
    cudaGetSymbolAddress(&p, devsym);
    return (float*)p;
}

extern "C" void kernel_launch(void* const* d_in, const int* in_sizes, int n_in,
                              void* d_out, int out_size) {
    (void)in_sizes; (void)n_in; (void)out_size;
    const float* x        = (const float*)d_in[0];
    const float* y        = (const float*)d_in[1];
    const int*   label    = (const int*)d_in[2];
    const float* expand_W = (const float*)d_in[3];
    const float* expand_b = (const float*)d_in[4];
    const float* eWi0     = (const float*)d_in[5];
    const float* eWh0     = (const float*)d_in[6];
    const float* eb0      = (const float*)d_in[7];
    const float* eWi1     = (const float*)d_in[8];
    const float* eWh1     = (const float*)d_in[9];
    const float* eb1      = (const float*)d_in[10];
    const float* dWi0     = (const float*)d_in[11];
    const float* dWh0     = (const float*)d_in[12];
    const float* db0      = (const float*)d_in[13];
    const float* dWi1     = (const float*)d_in[14];
    const float* dWh1     = (const float*)d_in[15];
    const float* db1      = (const float*)d_in[16];
    const float* attn_W   = (const float*)d_in[17];
    const float* attn_b   = (const float*)d_in[18];
    const float* attn_v   = (const float*)d_in[19];
    const float* concat_W = (const float*)d_in[20];
    const float* concat_b = (const float*)d_in[21];
    const float* out_W    = (const float*)d_in[22];
    const float* out_b    = (const float*)d_in[23];

    float* Gx     = symaddr(&g_Gx);
    float* out0   = symaddr(&g_out0);
    float* outenc = symaddr(&g_outenc);
    float* E2     = symaddr(&g_E2);
    float* Wc     = symaddr(&g_Wc);
    float* bc     = symaddr(&g_bc);
    float* hT     = symaddr(&g_hT);
    float* dh     = symaddr(&g_dh);
    float* dc     = symaddr(&g_dc);
    float* l0     = symaddr(&g_l0);
    float* cc     = symaddr(&g_cc);
    float* dbuf   = symaddr(&g_dbuf);
    float* co     = symaddr(&g_co);
    float* score  = symaddr(&g_score);
    float* loss   = symaddr(&g_loss);
    float* bar    = symaddr(&g_bar);

    cudaFuncSetAttribute(enc_persist2, cudaFuncAttributeMaxDynamicSharedMemorySize,
                         ENC_SMEM_BYTES);

    const int S4 = 4 * BH;
    const int HT0 = 2 * 516 * 64;   // parity-0 region of hT
    const int NBAR = NBLK * 32 + 32;

    zero_kernel<<<1, 32>>>(loss, 1);

    // layer 0: fold expand into Wi, K=4 gate precompute
    fold0_kernel<<<(G8 + 127) / 128, 128>>>(eWi0, expand_W, expand_b, eb0, Wc, bc);
    gx0_kernel<<<dim3(33, TB / 64), 256>>>(x, Wc, bc, Gx);
    zero_kernel<<<(NBAR + 255) / 256, 256>>>(bar, NBAR);
    zero_kernel<<<(HT0 + 255) / 256, 256>>>(hT, HT0);
    enc_persist2<<<dim3(74, 2), 512, ENC_SMEM_BYTES>>>(Gx, eWh0, hT, out0, dh, dc);

    // layer 1
    mma_nt_kernel<<<dim3((G8 + 127) / 128, TB / 128), 256>>>(
        TB, G8, H2, out0, H2, eWi1, H2, eb1, Gx, G8);
    zero_kernel<<<(NBAR + 255) / 256, 256>>>(bar, NBAR);
    zero_kernel<<<(HT0 + 255) / 256, 256>>>(hT, HT0);
    enc_persist2<<<dim3(74, 2), 512, ENC_SMEM_BYTES>>>(Gx, eWh1, hT, outenc,
                                                       dh + 2 * BH, dc + 2 * BH);

    // attention precompute
    mma_nt_kernel<<<dim3((H2 + 127) / 128, TB / 128), 256>>>(
        TB, H2, H2, outenc, H2, attn_W + H2, G4, attn_b, E2, H2);

    // decoder
    for (int ts = 0; ts < NY; ts++) {
        int pp = (ts & 1) * S4, np = ((ts + 1) & 1) * S4;
        dec_cell_kernel<<<dim3(129, 2), 256>>>(
            y + (size_t)ts * B * SEQ, SEQ, dWi0, dWh0, db0,
            dh + pp, dh + np, dc + pp, dc + np, l0, H2);
        dec_cell_kernel<<<dim3(129, 2), 256>>>(
            l0, H2, dWi1, dWh1, db1,
            dh + pp + 2 * BH, dh + np + 2 * BH, dc + pp + 2 * BH, dc + np + 2 * BH,
            cc, 2 * H2);
        skinny64_nt_kernel<<<(H2 + 15) / 16, 256>>>(
            H2, H2, cc, 2 * H2, attn_W, G4, nullptr, dbuf, H2, 0);
        score_kernel<<<TB / 8, 256>>>(E2, dbuf, attn_v, score);
        attn_kernel<<<B, 512>>>(score, outenc, cc);
        skinny64_nt_kernel<<<(H2 + 15) / 16, 256>>>(
            H2, G4, cc, 2 * H2, concat_W, G4, concat_b, co, H2, 1);
        ce_fused_kernel<<<1, 1024>>>(co, out_W, out_b, label + ts * B, loss);
    }

    write_out_kernel<<<1, 1>>>((float*)d_out, loss);
}

// round 14
// speedup vs baseline: 1.1329x; 1.0138x over previous
#include <cuda_runtime.h>
#include <math.h>
#include <stdint.h>

#define H   516
#define T   512
#define B   64
#define NY  20
#define SEQ 20
#define G4  2064
#define H2  1032
#define TB  32768
#define G8  4128
#define BH  33024

#define BARSZ 4800   /* 2*74*32 slots + 2 release words (32-spaced) */

// enc smem carve (floats)
#define OFF_W  0
#define SZ_W   (32 * 517)
#define OFF_H  (OFF_W + SZ_W)
#define SZ_H   (516 * 64)
#define OFF_G  (OFF_H + SZ_H)
#define SZ_G   (2 * 64 * 33)
#define ENC_SMEM_BYTES ((OFF_G + SZ_G) * 4)

typedef unsigned long long ULL;

__device__ float g_Gx[TB * G8];
__device__ float g_out0[TB * H2];
__device__ float g_outenc[TB * H2];
__device__ float g_E2[TB * H2];
__device__ float g_Wc[G8 * 4];
__device__ float g_bc[G8];
__device__ float g_hT[2 * 2 * 516 * 64];    // [parity][dir][k][b]
__device__ float g_dh[2 * 4 * BH];
__device__ float g_dc[2 * 4 * BH];
__device__ float g_l0[B * H2];
__device__ float g_cc[B * 2 * H2];
__device__ float g_dbuf[B * H2];
__device__ float g_co[B * H2];
__device__ float g_score[B * T];
__device__ float g_loss[1];
__device__ unsigned g_bar[BARSZ];

__device__ __forceinline__ void fma2(ULL& d, ULL a, ULL b) {
    asm("fma.rn.f32x2 %0, %1, %2, %0;" : "+l"(d) : "l"(a), "l"(b));
}
__device__ __forceinline__ ULL pack2(float lo, float hi) {
    ULL r; asm("mov.b64 %0, {%1, %2};" : "=l"(r) : "f"(lo), "f"(hi)); return r;
}
__device__ __forceinline__ void unpack2(ULL v, float& lo, float& hi) {
    asm("mov.b64 {%0, %1}, %2;" : "=f"(lo), "=f"(hi) : "l"(v));
}
__device__ __forceinline__ uint32_t to_tf32(float x) {
    uint32_t r; asm("cvt.rna.tf32.f32 %0, %1;" : "=r"(r) : "f"(x)); return r;
}
__device__ __forceinline__ float ftanh(float x) {
    float r; asm("tanh.approx.f32 %0, %1;" : "=f"(r) : "f"(x)); return r;
}
__device__ __forceinline__ uint32_t smem_u32(const void* p) {
    uint32_t a;
    asm("{ .reg .u64 t; cvta.to.shared.u64 t, %1; cvt.u32.u64 %0, t; }"
        : "=r"(a) : "l"(p));
    return a;
}

// per-direction grid barrier: 74 blocks, slot per block (128B apart),
// block 0 of the direction aggregates, single release word per dir.
__device__ __forceinline__ void gbar2(int dir, int bx, int tid, unsigned target) {
    __syncthreads();
    unsigned* slots = g_bar + dir * (74 * 32);
    volatile unsigned* rel = (volatile unsigned*)(g_bar + 2 * 74 * 32 + dir * 32);
    if (bx == 0) {
        if (tid >= 1 && tid < 74) {
            while (*(volatile unsigned*)&slots[tid * 32] < target) __nanosleep(32);
        }
        __syncthreads();
        if (tid == 0) { __threadfence(); *rel = target; }
        __syncthreads();
    } else {
        if (tid == 0) {
            __threadfence();
            *(volatile unsigned*)&slots[bx * 32] = target;
            while (*rel < target) __nanosleep(32);
            __threadfence();
        }
        __syncthreads();
    }
}

__global__ void zero_kernel(float* p, int n) {
    int i = blockIdx.x * 256 + threadIdx.x;
    if (i < n) p[i] = 0.f;
}
__global__ void zero_all_kernel(float* loss, unsigned* bar, float* hT) {
    int i = blockIdx.x * 256 + threadIdx.x;
    if (i == 0) loss[0] = 0.f;
    if (i < BARSZ) bar[i] = 0u;
    if (i < 2 * 516 * 64) hT[i] = 0.f;
}
__global__ void write_out_kernel(float* out, const float* loss) { out[0] = loss[0]; }

__global__ void fold0_kernel(const float* __restrict__ eWi0, const float* __restrict__ We,
                             const float* __restrict__ be, const float* __restrict__ eb0,
                             float* __restrict__ Wc, float* __restrict__ bc) {
    int i = blockIdx.x * 128 + threadIdx.x;
    if (i >= G8) return;
    const float* wi = eWi0 + (size_t)i * 256;
    float a0 = 0.f, a1 = 0.f, a2 = 0.f, a3 = 0.f, ab = eb0[i];
    for (int k = 0; k < 256; k++) {
        float w = wi[k];
        float4 we4 = *(const float4*)(We + k * 4);
        a0 = fmaf(w, we4.x, a0); a1 = fmaf(w, we4.y, a1);
        a2 = fmaf(w, we4.z, a2); a3 = fmaf(w, we4.w, a3);
        ab = fmaf(w, be[k], ab);
    }
    *(float4*)(Wc + (size_t)i * 4) = make_float4(a0, a1, a2, a3);
    bc[i] = ab;
}

__global__ void gx0_kernel(const float* __restrict__ x, const float* __restrict__ Wc,
                           const float* __restrict__ bc, float* __restrict__ Gx) {
    __shared__ float4 xs[64];
    __shared__ float4 ws[128];
    __shared__ float bs[128];
    int tid = threadIdx.x;
    int r0 = blockIdx.y * 64, c0 = blockIdx.x * 128;
    if (tid < 64) xs[tid] = *(const float4*)(x + (size_t)(r0 + tid) * 4);
    if (tid >= 128) {
        int q = tid - 128; int c = c0 + q;
        if (c < G8) { ws[q] = *(const float4*)(Wc + (size_t)c * 4); bs[q] = bc[c]; }
        else { ws[q] = make_float4(0.f, 0.f, 0.f, 0.f); bs[q] = 0.f; }
    }
    __syncthreads();
    int tc = (tid & 31) * 4, tr = (tid >> 5) * 8;
    int cg = c0 + tc;
    if (cg >= G8) return;
    float4 w0 = ws[tc], w1 = ws[tc + 1], w2 = ws[tc + 2], w3 = ws[tc + 3];
    float b0 = bs[tc], b1 = bs[tc + 1], b2 = bs[tc + 2], b3 = bs[tc + 3];
#pragma unroll
    for (int i = 0; i < 8; i++) {
        int r = r0 + tr + i;
        float4 xv = xs[tr + i];
        float4 o;
        o.x = fmaf(xv.x, w0.x, fmaf(xv.y, w0.y, fmaf(xv.z, w0.z, fmaf(xv.w, w0.w, b0))));
        o.y = fmaf(xv.x, w1.x, fmaf(xv.y, w1.y, fmaf(xv.z, w1.z, fmaf(xv.w, w1.w, b1))));
        o.z = fmaf(xv.x, w2.x, fmaf(xv.y, w2.y, fmaf(xv.z, w2.z, fmaf(xv.w, w2.w, b2))));
        o.w = fmaf(xv.x, w3.x, fmaf(xv.y, w3.y, fmaf(xv.z, w3.z, fmaf(xv.w, w3.w, b3))));
        *(float4*)(Gx + (size_t)r * G8 + cg) = o;
    }
}

// TF32 MMA GEMM: C = A @ Bm^T + bias
__global__ void __launch_bounds__(256, 2)
mma_nt_kernel(int M, int N, int K,
              const float* __restrict__ A, int lda,
              const float* __restrict__ Bm, int ldb,
              const float* __restrict__ bias,
              float* __restrict__ C, int ldc) {
    __shared__ uint32_t As[2][16][132];
    __shared__ uint32_t Bs[2][16][132];
    const int tid = threadIdx.x;
    const int lane = tid & 31, warp = tid >> 5;
    const int gid = lane >> 2, qid = lane & 3;
    const int wm = (warp & 1) * 64, wn = (warp >> 1) * 32;
    const int row0 = blockIdx.y * 128, col0 = blockIdx.x * 128;

    float acc[4][4][4];
#pragma unroll
    for (int mt = 0; mt < 4; mt++)
#pragma unroll
        for (int nt = 0; nt < 4; nt++)
#pragma unroll
            for (int i = 0; i < 4; i++) acc[mt][nt][i] = 0.f;

    const int nk = (K + 15) / 16;
    float4 stA[2], stB[2];

    auto LOADG = [&](int ch) {
        int k0 = ch * 16;
#pragma unroll
        for (int i = 0; i < 2; i++) {
            int q = tid * 2 + i;
            int r = q >> 2, c = (q & 3) * 4;
            if (k0 + c + 3 < K) {
                stA[i] = *(const float4*)(A + (size_t)(row0 + r) * lda + k0 + c);
            } else {
                float tmp[4];
#pragma unroll
                for (int j = 0; j < 4; j++)
                    tmp[j] = (k0 + c + j < K) ? A[(size_t)(row0 + r) * lda + k0 + c + j] : 0.f;
                stA[i] = *(float4*)tmp;
            }
            int n = col0 + r;
            if (n < N && k0 + c + 3 < K) {
                stB[i] = *(const float4*)(Bm + (size_t)n * ldb + k0 + c);
            } else {
                float tmp[4];
#pragma unroll
                for (int j = 0; j < 4; j++)
                    tmp[j] = (n < N && k0 + c + j < K) ? Bm[(size_t)n * ldb + k0 + c + j] : 0.f;
                stB[i] = *(float4*)tmp;
            }
        }
    };
    auto STORE = [&](int buf) {
#pragma unroll
        for (int i = 0; i < 2; i++) {
            int q = tid * 2 + i;
            int r = q >> 2, c = (q & 3) * 4;
            const float* va = (const float*)&stA[i];
            const float* vb = (const float*)&stB[i];
#pragma unroll
            for (int j = 0; j < 4; j++) {
                As[buf][c + j][r] = to_tf32(va[j]);
                Bs[buf][c + j][r] = to_tf32(vb[j]);
            }
        }
    };
    auto COMPUTE = [&](int buf) {
#pragma unroll
        for (int ks = 0; ks < 2; ks++) {
            const int kb = ks * 8 + qid;
            uint32_t af[4][4], bf[4][2];
#pragma unroll
            for (int mt = 0; mt < 4; mt++) {
                int m0 = wm + mt * 16 + gid;
                af[mt][0] = As[buf][kb][m0];     af[mt][1] = As[buf][kb][m0 + 8];
                af[mt][2] = As[buf][kb + 4][m0]; af[mt][3] = As[buf][kb + 4][m0 + 8];
            }
#pragma unroll
            for (int nt = 0; nt < 4; nt++) {
                int n0 = wn + nt * 8 + gid;
                bf[nt][0] = Bs[buf][kb][n0]; bf[nt][1] = Bs[buf][kb + 4][n0];
            }
#pragma unroll
            for (int mt = 0; mt < 4; mt++)
#pragma unroll
                for (int nt = 0; nt < 4; nt++) {
                    asm volatile(
                        "mma.sync.aligned.m16n8k8.row.col.f32.tf32.tf32.f32 "
                        "{%0,%1,%2,%3}, {%4,%5,%6,%7}, {%8,%9}, {%0,%1,%2,%3};"
                        : "+f"(acc[mt][nt][0]), "+f"(acc[mt][nt][1]),
                          "+f"(acc[mt][nt][2]), "+f"(acc[mt][nt][3])
                        : "r"(af[mt][0]), "r"(af[mt][1]),
                          "r"(af[mt][2]), "r"(af[mt][3]),
                          "r"(bf[nt][0]), "r"(bf[nt][1]));
                }
        }
    };

    LOADG(0); STORE(0); __syncthreads();
    for (int ch = 0; ch < nk; ch++) {
        if (ch + 1 < nk) LOADG(ch + 1);
        COMPUTE(ch & 1);
        if (ch + 1 < nk) STORE((ch + 1) & 1);
        __syncthreads();
    }
#pragma unroll
    for (int mt = 0; mt < 4; mt++) {
        int r1 = row0 + wm + mt * 16 + gid;
#pragma unroll
        for (int nt = 0; nt < 4; nt++) {
            int c0 = col0 + wn + nt * 8 + qid * 2;
            float b0 = 0.f, b1 = 0.f;
            if (bias) {
                if (c0 < N) b0 = bias[c0];
                if (c0 + 1 < N) b1 = bias[c0 + 1];
            }
            if (c0 < N) {
                C[(size_t)r1 * ldc + c0] = acc[mt][nt][0] + b0;
                C[(size_t)(r1 + 8) * ldc + c0] = acc[mt][nt][2] + b0;
            }
            if (c0 + 1 < N) {
                C[(size_t)r1 * ldc + c0 + 1] = acc[mt][nt][1] + b1;
                C[(size_t)(r1 + 8) * ldc + c0 + 1] = acc[mt][nt][3] + b1;
            }
        }
    }
}

// persistent encoder layer: grid (74, 2), 512 thr, 1 block/SM, c in regs.
// bar_base makes barrier targets monotone across layers (no bar re-zero).
__global__ void __launch_bounds__(512, 1)
enc_persist2(const float* __restrict__ Gx,   // [t*B+b][G8]
             const float* __restrict__ Wh,   // [2][G4][H]
             float* __restrict__ hT,         // [2][2][516][64]
             float* __restrict__ outseq,     // [T][B][H2]
             float* __restrict__ dh_fin,     // [2 dir][B][H]
             float* __restrict__ dc_fin,
             unsigned bar_base) {
    extern __shared__ float smem[];
    float* Wsf = smem + OFF_W;   // [32][517] row = g*8+jj
    float* hTs = smem + OFF_H;   // [516][64]
    float* gsm = smem + OFF_G;   // [2][64][33]

    const int dir = blockIdx.y, bx = blockIdx.x;
    const int j0 = bx * 7;
    const int tid = threadIdx.x;
    const uint32_t hTs_b = smem_u32(hTs);

    const int warp = tid >> 5, lane = tid & 31;
    const int bg = warp >> 1, ks = warp & 1;
    const int b0 = bg * 8;
    float* wrow = Wsf + lane * 517 + ks * 258;

    const int cb = tid & 63, cjj = tid >> 6;
    const int cj = j0 + cjj;
    const bool cell_act = (cjj < 7) && (cj < H);

    const float* whd = Wh + (size_t)dir * G4 * H;
    for (int idx = tid; idx < 32 * 517; idx += 512) {
        int r = idx / 517, k = idx - r * 517;
        int g = r >> 3, jj = r & 7;
        float wv = 0.f;
        if (jj < 7 && (j0 + jj) < H && k < H)
            wv = whd[(size_t)(g * H + j0 + jj) * H + k];
        Wsf[idx] = wv;
    }
    __syncthreads();

    float creg = 0.f;

    for (int s = 0; s < T; s++) {
        const int t = dir ? (T - 1 - s) : s;
        const int rp = s & 1, wp = (s + 1) & 1;

        // prefetch gate inputs (independent of h)
        float gxi = 0.f, gxf = 0.f, gxg = 0.f, gxo = 0.f;
        if (cell_act) {
            const float* gx = Gx + ((size_t)t * B + cb) * G8 + dir * G4 + cj;
            gxi = gx[0]; gxf = gx[H]; gxg = gx[2 * H]; gxo = gx[3 * H];
        }

        // stage h^T (132KB) via cp.async
        {
            const float4* src = (const float4*)(hT + ((size_t)rp * 2 + dir) * (516 * 64));
            for (int idx = tid; idx < (516 * 64) / 4; idx += 512) {
                uint32_t d = hTs_b + (uint32_t)idx * 16;
                asm volatile("cp.async.cg.shared.global [%0], [%1], 16;"
                             :: "r"(d), "l"(src + idx));
            }
            asm volatile("cp.async.commit_group;\n\tcp.async.wait_group 0;" ::: "memory");
        }
        __syncthreads();

        // GEMM: row=lane, 8 batches, half-K
        ULL a0 = 0ull, a1 = 0ull, a2 = 0ull, a3 = 0ull;
        {
            const float* hb = hTs + (size_t)(ks * 258) * 64 + b0;
#pragma unroll 2
            for (int k = 0; k < 258; k++) {
                float w = wrow[k];
                ULL wpk = pack2(w, w);
                longlong2 v0 = *(const longlong2*)(hb);
                longlong2 v1 = *(const longlong2*)(hb + 4);
                fma2(a0, wpk, (ULL)v0.x);
                fma2(a1, wpk, (ULL)v0.y);
                fma2(a2, wpk, (ULL)v1.x);
                fma2(a3, wpk, (ULL)v1.y);
                hb += 64;
            }
        }
        {
            float v0, v1;
            float* g = gsm + (size_t)(ks * 64 + b0) * 33 + lane;
            unpack2(a0, v0, v1); g[0] = v0;   g[33] = v1;
            unpack2(a1, v0, v1); g[66] = v0;  g[99] = v1;
            unpack2(a2, v0, v1); g[132] = v0; g[165] = v1;
            unpack2(a3, v0, v1); g[198] = v0; g[231] = v1;
        }
        __syncthreads();

        // cell
        if (cell_act) {
            const float* ga = gsm + (size_t)cb * 33;
            const float* gb = gsm + (size_t)(64 + cb) * 33;
            float gi = ga[cjj]      + gb[cjj]      + gxi;
            float gf = ga[8 + cjj]  + gb[8 + cjj]  + gxf;
            float gg = ga[16 + cjj] + gb[16 + cjj] + gxg;
            float go = ga[24 + cjj] + gb[24 + cjj] + gxo;
            float si = 1.f / (1.f + expf(-gi));
            float sf = 1.f / (1.f + expf(-gf));
            float so = 1.f / (1.f + expf(-go));
            float cn = fmaf(sf, creg, si * tanhf(gg));
            float hn = so * tanhf(cn);
            creg = cn;
            hT[((size_t)wp * 2 + dir) * (516 * 64) + (size_t)cj * 64 + cb] = hn;
            outseq[((size_t)t * B + cb) * H2 + dir * H + cj] = hn;
            if (s == T - 1) {
                dh_fin[dir * BH + cb * H + cj] = hn;
                dc_fin[dir * BH + cb * H + cj] = cn;
            }
        }

        if (s < T - 1) gbar2(dir, bx, tid, bar_base + (unsigned)(s + 1));
    }
}

__global__ void dec_cell_kernel(const float* __restrict__ x, int Kx,
                                const float* __restrict__ Wi, const float* __restrict__ Wh,
                                const float* __restrict__ bias,
                                const float* __restrict__ hprev, float* __restrict__ hnext,
                                const float* __restrict__ cprev, float* __restrict__ cnext,
                                float* __restrict__ outcat, int outld) {
    const int dir = blockIdx.y;
    const int j0 = blockIdx.x * 4;
    const int tid = threadIdx.x;
    const int tx = tid & 15, ty = tid >> 4, rb = ty * 4;

    __shared__ float As[12][68];
    __shared__ float Ws[16][13];
    __shared__ float gsm[64][17];

    float acc0 = 0.f, acc1 = 0.f, acc2 = 0.f, acc3 = 0.f;

    for (int ph = 0; ph < 2; ph++) {
        const float* A = (ph == 0) ? x : (hprev + dir * BH);
        const int K = (ph == 0) ? Kx : H;
        const float* W = (ph == 0) ? (Wi + (size_t)dir * G4 * Kx) : (Wh + (size_t)dir * G4 * H);
        for (int k0 = 0; k0 < K; k0 += 12) {
            int rem = K - k0; if (rem > 12) rem = 12;
            for (int idx = tid; idx < 64 * 12; idx += 256) {
                int bb = idx / 12, kk = idx % 12;
                As[kk][bb] = (kk < rem) ? A[bb * K + k0 + kk] : 0.f;
            }
            if (tid < 192) {
                int r = tid / 12, kk = tid % 12;
                int rq = r >> 2, ru = r & 3;
                float wv = 0.f;
                if (kk < rem) wv = W[(size_t)(rq * H + j0 + ru) * K + k0 + kk];
                Ws[r][kk] = wv;
            }
            __syncthreads();
#pragma unroll
            for (int kk = 0; kk < 12; kk++) {
                float4 hv = *(const float4*)&As[kk][rb];
                float w = Ws[tx][kk];
                acc0 = fmaf(hv.x, w, acc0);
                acc1 = fmaf(hv.y, w, acc1);
                acc2 = fmaf(hv.z, w, acc2);
                acc3 = fmaf(hv.w, w, acc3);
            }
            __syncthreads();
        }
    }
    gsm[rb + 0][tx] = acc0; gsm[rb + 1][tx] = acc1;
    gsm[rb + 2][tx] = acc2; gsm[rb + 3][tx] = acc3;
    __syncthreads();
    {
        int bb = tid >> 2, uu = tid & 3;
        int j = j0 + uu;
        const float* bz = bias + dir * G4;
        float gi = gsm[bb][uu]      + bz[j];
        float gf = gsm[bb][4 + uu]  + bz[H + j];
        float gg = gsm[bb][8 + uu]  + bz[2 * H + j];
        float go = gsm[bb][12 + uu] + bz[3 * H + j];
        float cp = cprev[dir * BH + bb * H + j];
        float si = 1.f / (1.f + expf(-gi));
        float sf = 1.f / (1.f + expf(-gf));
        float so = 1.f / (1.f + expf(-go));
        float cn = fmaf(sf, cp, si * tanhf(gg));
        float hn = so * tanhf(cn);
        cnext[dir * BH + bb * H + j] = cn;
        hnext[dir * BH + bb * H + j] = hn;
        outcat[bb * outld + dir * H + j] = hn;
    }
}

__global__ void skinny64_nt_kernel(int N, int K,
                                   const float* __restrict__ A, int lda,
                                   const float* __restrict__ W, int ldw,
                                   const float* __restrict__ bias,
                                   float* __restrict__ C, int ldc, int act) {
    __shared__ float As[16][68];
    __shared__ float Ws[16][17];
    const int tid = threadIdx.x;
    const int tx = tid & 15, ty = tid >> 4;
    const int col = blockIdx.x * 16 + tx;
    float acc[4] = {0.f, 0.f, 0.f, 0.f};
    for (int k0 = 0; k0 < K; k0 += 16) {
        for (int idx = tid; idx < 64 * 16; idx += 256) {
            int r = idx >> 4, kk = idx & 15;
            As[kk][r] = (k0 + kk < K) ? A[(size_t)r * lda + k0 + kk] : 0.f;
        }
        {
            int cix = tid & 15, kk = tid >> 4;
            int cg = blockIdx.x * 16 + cix;
            float wv = 0.f;
            if (cg < N && (k0 + kk) < K) wv = W[(size_t)cg * ldw + k0 + kk];
            Ws[cix][kk] = wv;
        }
        __syncthreads();
#pragma unroll
        for (int kk = 0; kk < 16; kk++) {
            float w = Ws[tx][kk];
            float4 a = *(const float4*)&As[kk][ty * 4];
            acc[0] = fmaf(a.x, w, acc[0]);
            acc[1] = fmaf(a.y, w, acc[1]);
            acc[2] = fmaf(a.z, w, acc[2]);
            acc[3] = fmaf(a.w, w, acc[3]);
        }
        __syncthreads();
    }
    if (col < N) {
#pragma unroll
        for (int i = 0; i < 4; i++) {
            int r = ty * 4 + i;
            float v = acc[i];
            if (bias) v += bias[col];
            if (act) v = tanhf(v);
            C[(size_t)r * ldc + col] = v;
        }
    }
}

__global__ void score_kernel(const float* __restrict__ E2, const float* __restrict__ dbuf,
                             const float* __restrict__ v, float* __restrict__ score) {
    int w = blockIdx.x * 8 + (threadIdx.x >> 5);
    int lane = threadIdx.x & 31;
    int bb = w & 63, t = w >> 6;
    const float4* e = (const float4*)(E2 + (size_t)w * H2);
    const float4* d = (const float4*)(dbuf + (size_t)bb * H2);
    const float4* vv = (const float4*)v;
    float s = 0.f;
    for (int q = lane; q < H2 / 4; q += 32) {
        float4 ev = e[q], dv = d[q], vq = vv[q];
        s = fmaf(vq.x, ftanh(ev.x + dv.x), s);
        s = fmaf(vq.y, ftanh(ev.y + dv.y), s);
        s = fmaf(vq.z, ftanh(ev.z + dv.z), s);
        s = fmaf(vq.w, ftanh(ev.w + dv.w), s);
    }
#pragma unroll
    for (int o = 16; o > 0; o >>= 1) s += __shfl_down_sync(0xffffffffu, s, o);
    if (lane == 0) score[bb * T + t] = s;
}

__global__ void attn_kernel(const float* __restrict__ score, const float* __restrict__ enc,
                            float* __restrict__ cc) {
    __shared__ float sm[T];
    __shared__ float aws[T];
    int bb = blockIdx.x, tid = threadIdx.x;
    float v = score[bb * T + tid];
    sm[tid] = v;
    __syncthreads();
    for (int st = 256; st > 0; st >>= 1) {
        if (tid < st) sm[tid] = fmaxf(sm[tid], sm[tid + st]);
        __syncthreads();
    }
    float mx = sm[0];
    __syncthreads();
    float e = expf(v - mx);
    sm[tid] = e;
    __syncthreads();
    for (int st = 256; st > 0; st >>= 1) {
        if (tid < st) sm[tid] += sm[tid + st];
        __syncthreads();
    }
    aws[tid] = e / sm[0];
    __syncthreads();
    float acc[3] = {0.f, 0.f, 0.f};
    for (int t = 0; t < T; t++) {
        float wt = aws[t];
        const float* ep = enc + ((size_t)t * B + bb) * H2;
#pragma unroll
        for (int j = 0; j < 3; j++) {
            int hh = tid + j * 512;
            if (hh < H2) acc[j] = fmaf(wt, ep[hh], acc[j]);
        }
    }
#pragma unroll
    for (int j = 0; j < 3; j++) {
        int hh = tid + j * 512;
        if (hh < H2) cc[bb * (2 * H2) + H2 + hh] = acc[j];
    }
}

__global__ void ce_fused_kernel(const float* __restrict__ co, const float* __restrict__ out_W,
                                const float* __restrict__ out_b, const int* __restrict__ lab,
                                float* __restrict__ loss) {
    __shared__ float lg[64][20];
    __shared__ float red[64];
    int tid = threadIdx.x;
    int bb = tid >> 4, slot = tid & 15;
    for (int cix = slot; cix < SEQ; cix += 16) {
        const float* a = co + bb * H2;
        const float* w = out_W + cix * H2;
        float s = out_b[cix];
#pragma unroll 4
        for (int k = 0; k < H2; k++) s = fmaf(a[k], w[k], s);
        lg[bb][cix] = s;
    }
    __syncthreads();
    if (slot == 0) {
        float m = lg[bb][0];
#pragma unroll
        for (int i = 1; i < SEQ; i++) m = fmaxf(m, lg[bb][i]);
        float s = 0.f;
#pragma unroll
        for (int i = 0; i < SEQ; i++) s += expf(lg[bb][i] - m);
        red[bb] = -(lg[bb][lab[bb]] - m - logf(s));
    }
    __syncthreads();
    if (tid == 0) {
        float tot = 0.f;
        for (int i = 0; i < 64; i++) tot += red[i];
        loss[0] += tot / 64.f;
    }
}

static float* symaddr(const void* devsym) {
    void* p = nullptr;
    cudaGetSymbolAddress(&p, devsym);
    return (float*)p;
}

extern "C" void kernel_launch(void* const* d_in, const int* in_sizes, int n_in,
                              void* d_out, int out_size) {
    (void)in_sizes; (void)n_in; (void)out_size;
    const float* x        = (const float*)d_in[0];
    const float* y        = (const float*)d_in[1];
    const int*   label    = (const int*)d_in[2];
    const float* expand_W = (const float*)d_in[3];
    const float* expand_b = (const float*)d_in[4];
    const float* eWi0     = (const float*)d_in[5];
    const float* eWh0     = (const float*)d_in[6];
    const float* eb0      = (const float*)d_in[7];
    const float* eWi1     = (const float*)d_in[8];
    const float* eWh1     = (const float*)d_in[9];
    const float* eb1      = (const float*)d_in[10];
    const float* dWi0     = (const float*)d_in[11];
    const float* dWh0     = (const float*)d_in[12];
    const float* db0      = (const float*)d_in[13];
    const float* dWi1     = (const float*)d_in[14];
    const float* dWh1     = (const float*)d_in[15];
    const float* db1      = (const float*)d_in[16];
    const float* attn_W   = (const float*)d_in[17];
    const float* attn_b   = (const float*)d_in[18];
    const float* attn_v   = (const float*)d_in[19];
    const float* concat_W = (const float*)d_in[20];
    const float* concat_b = (const float*)d_in[21];
    const float* out_W    = (const float*)d_in[22];
    const float* out_b    = (const float*)d_in[23];

    float* Gx     = symaddr(&g_Gx);
    float* out0   = symaddr(&g_out0);
    float* outenc = symaddr(&g_outenc);
    float* E2     = symaddr(&g_E2);
    float* Wc     = symaddr(&g_Wc);
    float* bc     = symaddr(&g_bc);
    float* hT     = symaddr(&g_hT);
    float* dh     = symaddr(&g_dh);
    float* dc     = symaddr(&g_dc);
    float* l0     = symaddr(&g_l0);
    float* cc     = symaddr(&g_cc);
    float* dbuf   = symaddr(&g_dbuf);
    float* co     = symaddr(&g_co);
    float* score  = symaddr(&g_score);
    float* loss   = symaddr(&g_loss);
    unsigned* bar = (unsigned*)symaddr(&g_bar);

    cudaFuncSetAttribute(enc_persist2, cudaFuncAttributeMaxDynamicSharedMemorySize,
                         ENC_SMEM_BYTES);

    const int S4 = 4 * BH;
    const int HT0 = 2 * 516 * 64;   // parity-0 region of hT

    // Launch order matters: ncu -s 5 -c 1 captures OUR launch #3 → enc_persist2.
    fold0_kernel<<<(G8 + 127) / 128, 128>>>(eWi0, expand_W, expand_b, eb0, Wc, bc);  // #0
    gx0_kernel<<<dim3(33, TB / 64), 256>>>(x, Wc, bc, Gx);                           // #1
    zero_all_kernel<<<(HT0 + 255) / 256, 256>>>(loss, bar, hT);                      // #2
    enc_persist2<<<dim3(74, 2), 512, ENC_SMEM_BYTES>>>(                              // #3
        Gx, eWh0, hT, out0, dh, dc, 0u);

    mma_nt_kernel<<<dim3((G8 + 127) / 128, TB / 128), 256>>>(
        TB, G8, H2, out0, H2, eWi1, H2, eb1, Gx, G8);
    zero_kernel<<<(HT0 + 255) / 256, 256>>>(hT, HT0);
    enc_persist2<<<dim3(74, 2), 512, ENC_SMEM_BYTES>>>(
        Gx, eWh1, hT, outenc, dh + 2 * BH, dc + 2 * BH, (unsigned)T);

    mma_nt_kernel<<<dim3((H2 + 127) / 128, TB / 128), 256>>>(
        TB, H2, H2, outenc, H2, attn_W + H2, G4, attn_b, E2, H2);

    for (int ts = 0; ts < NY; ts++) {
        int pp = (ts & 1) * S4, np = ((ts + 1) & 1) * S4;
        dec_cell_kernel<<<dim3(129, 2), 256>>>(
            y + (size_t)ts * B * SEQ, SEQ, dWi0, dWh0, db0,
            dh + pp, dh + np, dc + pp, dc + np, l0, H2);
        dec_cell_kernel<<<dim3(129, 2), 256>>>(
            l0, H2, dWi1, dWh1, db1,
            dh + pp + 2 * BH, dh + np + 2 * BH, dc + pp + 2 * BH, dc + np + 2 * BH,
            cc, 2 * H2);
        skinny64_nt_kernel<<<(H2 + 15) / 16, 256>>>(
            H2, H2, cc, 2 * H2, attn_W, G4, nullptr, dbuf, H2, 0);
        score_kernel<<<TB / 8, 256>>>(E2, dbuf, attn_v, score);
        attn_kernel<<<B, 512>>>(score, outenc, cc);
        skinny64_nt_kernel<<<(H2 + 15) / 16, 256>>>(
            H2, G4, cc, 2 * H2, concat_W, G4, concat_b, co, H2, 1);
        ce_fused_kernel<<<1, 1024>>>(co, out_W, out_b, label + ts * B, loss);
    }

    write_out_kernel<<<1, 1>>>((float*)d_out, loss);
}

// round 15
// speedup vs baseline: 1.3950x; 1.2313x over previous
#include <cuda_runtime.h>
#include <math.h>
#include <stdint.h>

#define H   516
#define T   512
#define B   64
#define NY  20
#define SEQ 20
#define G4  2064
#define H2  1032
#define TB  32768
#define G8  4128
#define BH  33024

#define BARSZ 4800   /* 2*74*32 slots (+ spare) */

// enc dynamic smem carve (floats)
#define OFF_AF 0                       /* A fragments: 65 ch * 2 mt * 32 lane * 4 = 16640 */
#define SZ_AF  (65 * 2 * 32 * 4)
#define OFF_HT (OFF_AF + SZ_AF)        /* hTs: 520 rows * 68 cols = 35360 */
#define SZ_HT  (520 * 68)
#define OFF_GS (OFF_HT + SZ_HT)        /* gsm: 2 kh * 32 rows * 66 = 4224 */
#define SZ_GS  (2 * 32 * 66)
#define ENC_SMEM_FLOATS (OFF_GS + SZ_GS)
#define ENC_SMEM_BYTES  (ENC_SMEM_FLOATS * 4)   /* 224,896 B */

typedef unsigned long long ULL;

__device__ float g_Gx[TB * G8];
__device__ float g_out0[TB * H2];
__device__ float g_outenc[TB * H2];
__device__ float g_E2[TB * H2];
__device__ float g_Wc[G8 * 4];
__device__ float g_bc[G8];
__device__ float g_hT[2 * 2 * 516 * 64];    // [parity][dir][k][b]
__device__ float g_dh[2 * 4 * BH];
__device__ float g_dc[2 * 4 * BH];
__device__ float g_l0[B * H2];
__device__ float g_cc[B * 2 * H2];
__device__ float g_dbuf[B * H2];
__device__ float g_co[B * H2];
__device__ float g_score[B * T];
__device__ float g_loss[1];
__device__ unsigned g_bar[BARSZ];

__device__ __forceinline__ uint32_t to_tf32(float x) {
    uint32_t r; asm("cvt.rna.tf32.f32 %0, %1;" : "=r"(r) : "f"(x)); return r;
}
__device__ __forceinline__ float ftanh(float x) {
    float r; asm("tanh.approx.f32 %0, %1;" : "=f"(r) : "f"(x)); return r;
}
__device__ __forceinline__ uint32_t smem_u32(const void* p) {
    uint32_t a;
    asm("{ .reg .u64 t; cvta.to.shared.u64 t, %1; cvt.u32.u64 %0, t; }"
        : "=r"(a) : "l"(p));
    return a;
}
__device__ __forceinline__ void mma_tf32(float* acc, uint32_t a0, uint32_t a1,
                                         uint32_t a2, uint32_t a3,
                                         uint32_t b0, uint32_t b1) {
    asm volatile(
        "mma.sync.aligned.m16n8k8.row.col.f32.tf32.tf32.f32 "
        "{%0,%1,%2,%3}, {%4,%5,%6,%7}, {%8,%9}, {%0,%1,%2,%3};"
        : "+f"(acc[0]), "+f"(acc[1]), "+f"(acc[2]), "+f"(acc[3])
        : "r"(a0), "r"(a1), "r"(a2), "r"(a3), "r"(b0), "r"(b1));
}

__global__ void zero_kernel(float* p, int n) {
    int i = blockIdx.x * 256 + threadIdx.x;
    if (i < n) p[i] = 0.f;
}
__global__ void zero_all_kernel(float* loss, unsigned* bar, float* hT) {
    int i = blockIdx.x * 256 + threadIdx.x;
    if (i == 0) loss[0] = 0.f;
    if (i < BARSZ) bar[i] = 0u;
    if (i < 2 * 516 * 64) hT[i] = 0.f;
}
__global__ void write_out_kernel(float* out, const float* loss) { out[0] = loss[0]; }

__global__ void fold0_kernel(const float* __restrict__ eWi0, const float* __restrict__ We,
                             const float* __restrict__ be, const float* __restrict__ eb0,
                             float* __restrict__ Wc, float* __restrict__ bc) {
    int i = blockIdx.x * 128 + threadIdx.x;
    if (i >= G8) return;
    const float* wi = eWi0 + (size_t)i * 256;
    float a0 = 0.f, a1 = 0.f, a2 = 0.f, a3 = 0.f, ab = eb0[i];
    for (int k = 0; k < 256; k++) {
        float w = wi[k];
        float4 we4 = *(const float4*)(We + k * 4);
        a0 = fmaf(w, we4.x, a0); a1 = fmaf(w, we4.y, a1);
        a2 = fmaf(w, we4.z, a2); a3 = fmaf(w, we4.w, a3);
        ab = fmaf(w, be[k], ab);
    }
    *(float4*)(Wc + (size_t)i * 4) = make_float4(a0, a1, a2, a3);
    bc[i] = ab;
}

__global__ void gx0_kernel(const float* __restrict__ x, const float* __restrict__ Wc,
                           const float* __restrict__ bc, float* __restrict__ Gx) {
    __shared__ float4 xs[64];
    __shared__ float4 ws[128];
    __shared__ float bs[128];
    int tid = threadIdx.x;
    int r0 = blockIdx.y * 64, c0 = blockIdx.x * 128;
    if (tid < 64) xs[tid] = *(const float4*)(x + (size_t)(r0 + tid) * 4);
    if (tid >= 128) {
        int q = tid - 128; int c = c0 + q;
        if (c < G8) { ws[q] = *(const float4*)(Wc + (size_t)c * 4); bs[q] = bc[c]; }
        else { ws[q] = make_float4(0.f, 0.f, 0.f, 0.f); bs[q] = 0.f; }
    }
    __syncthreads();
    int tc = (tid & 31) * 4, tr = (tid >> 5) * 8;
    int cg = c0 + tc;
    if (cg >= G8) return;
    float4 w0 = ws[tc], w1 = ws[tc + 1], w2 = ws[tc + 2], w3 = ws[tc + 3];
    float b0 = bs[tc], b1 = bs[tc + 1], b2 = bs[tc + 2], b3 = bs[tc + 3];
#pragma unroll
    for (int i = 0; i < 8; i++) {
        int r = r0 + tr + i;
        float4 xv = xs[tr + i];
        float4 o;
        o.x = fmaf(xv.x, w0.x, fmaf(xv.y, w0.y, fmaf(xv.z, w0.z, fmaf(xv.w, w0.w, b0))));
        o.y = fmaf(xv.x, w1.x, fmaf(xv.y, w1.y, fmaf(xv.z, w1.z, fmaf(xv.w, w1.w, b1))));
        o.z = fmaf(xv.x, w2.x, fmaf(xv.y, w2.y, fmaf(xv.z, w2.z, fmaf(xv.w, w2.w, b2))));
        o.w = fmaf(xv.x, w3.x, fmaf(xv.y, w3.y, fmaf(xv.z, w3.z, fmaf(xv.w, w3.w, b3))));
        *(float4*)(Gx + (size_t)r * G8 + cg) = o;
    }
}

// TF32 MMA GEMM: C = A @ Bm^T + bias (feed-forward path, unchanged)
__global__ void __launch_bounds__(256, 2)
mma_nt_kernel(int M, int N, int K,
              const float* __restrict__ A, int lda,
              const float* __restrict__ Bm, int ldb,
              const float* __restrict__ bias,
              float* __restrict__ C, int ldc) {
    __shared__ uint32_t As[2][16][132];
    __shared__ uint32_t Bs[2][16][132];
    const int tid = threadIdx.x;
    const int lane = tid & 31, warp = tid >> 5;
    const int gid = lane >> 2, qid = lane & 3;
    const int wm = (warp & 1) * 64, wn = (warp >> 1) * 32;
    const int row0 = blockIdx.y * 128, col0 = blockIdx.x * 128;

    float acc[4][4][4];
#pragma unroll
    for (int mt = 0; mt < 4; mt++)
#pragma unroll
        for (int nt = 0; nt < 4; nt++)
#pragma unroll
            for (int i = 0; i < 4; i++) acc[mt][nt][i] = 0.f;

    const int nk = (K + 15) / 16;
    float4 stA[2], stB[2];

    auto LOADG = [&](int ch) {
        int k0 = ch * 16;
#pragma unroll
        for (int i = 0; i < 2; i++) {
            int q = tid * 2 + i;
            int r = q >> 2, c = (q & 3) * 4;
            if (k0 + c + 3 < K) {
                stA[i] = *(const float4*)(A + (size_t)(row0 + r) * lda + k0 + c);
            } else {
                float tmp[4];
#pragma unroll
                for (int j = 0; j < 4; j++)
                    tmp[j] = (k0 + c + j < K) ? A[(size_t)(row0 + r) * lda + k0 + c + j] : 0.f;
                stA[i] = *(float4*)tmp;
            }
            int n = col0 + r;
            if (n < N && k0 + c + 3 < K) {
                stB[i] = *(const float4*)(Bm + (size_t)n * ldb + k0 + c);
            } else {
                float tmp[4];
#pragma unroll
                for (int j = 0; j < 4; j++)
                    tmp[j] = (n < N && k0 + c + j < K) ? Bm[(size_t)n * ldb + k0 + c + j] : 0.f;
                stB[i] = *(float4*)tmp;
            }
        }
    };
    auto STORE = [&](int buf) {
#pragma unroll
        for (int i = 0; i < 2; i++) {
            int q = tid * 2 + i;
            int r = q >> 2, c = (q & 3) * 4;
            const float* va = (const float*)&stA[i];
            const float* vb = (const float*)&stB[i];
#pragma unroll
            for (int j = 0; j < 4; j++) {
                As[buf][c + j][r] = to_tf32(va[j]);
                Bs[buf][c + j][r] = to_tf32(vb[j]);
            }
        }
    };
    auto COMPUTE = [&](int buf) {
#pragma unroll
        for (int ks = 0; ks < 2; ks++) {
            const int kb = ks * 8 + qid;
            uint32_t af[4][4], bf[4][2];
#pragma unroll
            for (int mt = 0; mt < 4; mt++) {
                int m0 = wm + mt * 16 + gid;
                af[mt][0] = As[buf][kb][m0];     af[mt][1] = As[buf][kb][m0 + 8];
                af[mt][2] = As[buf][kb + 4][m0]; af[mt][3] = As[buf][kb + 4][m0 + 8];
            }
#pragma unroll
            for (int nt = 0; nt < 4; nt++) {
                int n0 = wn + nt * 8 + gid;
                bf[nt][0] = Bs[buf][kb][n0]; bf[nt][1] = Bs[buf][kb + 4][n0];
            }
#pragma unroll
            for (int mt = 0; mt < 4; mt++)
#pragma unroll
                for (int nt = 0; nt < 4; nt++)
                    mma_tf32(acc[mt][nt], af[mt][0], af[mt][1], af[mt][2], af[mt][3],
                             bf[nt][0], bf[nt][1]);
        }
    };

    LOADG(0); STORE(0); __syncthreads();
    for (int ch = 0; ch < nk; ch++) {
        if (ch + 1 < nk) LOADG(ch + 1);
        COMPUTE(ch & 1);
        if (ch + 1 < nk) STORE((ch + 1) & 1);
        __syncthreads();
    }
#pragma unroll
    for (int mt = 0; mt < 4; mt++) {
        int r1 = row0 + wm + mt * 16 + gid;
#pragma unroll
        for (int nt = 0; nt < 4; nt++) {
            int c0 = col0 + wn + nt * 8 + qid * 2;
            float b0 = 0.f, b1 = 0.f;
            if (bias) {
                if (c0 < N) b0 = bias[c0];
                if (c0 + 1 < N) b1 = bias[c0 + 1];
            }
            if (c0 < N) {
                C[(size_t)r1 * ldc + c0] = acc[mt][nt][0] + b0;
                C[(size_t)(r1 + 8) * ldc + c0] = acc[mt][nt][2] + b0;
            }
            if (c0 + 1 < N) {
                C[(size_t)r1 * ldc + c0 + 1] = acc[mt][nt][1] + b1;
                C[(size_t)(r1 + 8) * ldc + c0 + 1] = acc[mt][nt][3] + b1;
            }
        }
    }
}

// persistent encoder layer v3: tensor-core recurrent GEMM + flat all-poll barrier.
// grid (74, 2 dirs), 512 threads, 1 block/SM.
__global__ void __launch_bounds__(512, 1)
enc_persist3(const float* __restrict__ Gx,   // [t*B+b][G8]
             const float* __restrict__ Wh,   // [2][G4][H]
             float* __restrict__ hT,         // [2 parity][2 dir][516][64]
             float* __restrict__ outseq,     // [T][B][H2]
             float* __restrict__ dh_fin,     // [2 dir][B][H]
             float* __restrict__ dc_fin,
             unsigned bar_base) {
    extern __shared__ float smem[];
    float* AF = smem + OFF_AF;            // A frags [65][2][32][4] (tf32 bits)
    float* HT = smem + OFF_HT;            // hTs [520][68]
    float* GS = smem + OFF_GS;            // gsm [2][32][66]
    uint32_t* AFu = (uint32_t*)AF;

    const int dir = blockIdx.y, bx = blockIdx.x;
    const int j0 = bx * 7;
    const int tid = threadIdx.x;
    const uint32_t hTs_b = smem_u32(HT);

    const int warp = tid >> 5, lane = tid & 31;
    const int gid = lane >> 2, qid = lane & 3;
    const int nt = warp & 7, kh = warp >> 3;
    const int ch_lo = kh ? 33 : 0, ch_hi = kh ? 65 : 33;
    const int n0 = nt * 8 + gid;          // B frag n index
    const int cw = nt * 8 + qid * 2;      // D col base

    const int cb = tid & 63, cjj = tid >> 6;   // cell mapping
    const int cj = j0 + cjj;
    const bool cell_act = (cjj < 7) && (cj < H);

    unsigned* slots = g_bar + dir * (74 * 32);

    // ---- one-time: zero hTs pad rows + build A fragments (tf32) ----
    for (int i = tid; i < SZ_HT; i += 512) HT[i] = 0.f;
    {
        const float* whd = Wh + (size_t)dir * G4 * H;
        for (int e = tid; e < 65 * 256; e += 512) {
            int ch = e >> 8;
            int rem = e & 255;
            int mt = rem >> 7;
            int l = (rem >> 2) & 31;
            int v = rem & 3;
            int lg = l >> 2, lq = l & 3;
            int k = ch * 8 + lq + ((v >= 2) ? 4 : 0);
            int r = mt * 16 + lg + ((v & 1) ? 8 : 0);
            int g = r >> 3, jj = r & 7;
            float wv = 0.f;
            if (jj < 7 && (j0 + jj) < H && k < H)
                wv = whd[(size_t)(g * H + j0 + jj) * H + k];
            AFu[e] = to_tf32(wv);
        }
    }
    __syncthreads();

    float creg = 0.f;

    for (int s = 0; s < T; s++) {
        const int t = dir ? (T - 1 - s) : s;
        const int rp = s & 1, wp = (s + 1) & 1;

        // prefetch gate inputs (independent of h)
        float gxi = 0.f, gxf = 0.f, gxg = 0.f, gxo = 0.f;
        if (cell_act) {
            const float* gx = Gx + ((size_t)t * B + cb) * G8 + dir * G4 + cj;
            gxi = gx[0]; gxf = gx[H]; gxg = gx[2 * H]; gxo = gx[3 * H];
        }

        // stage h^T (132KB fp32) into padded hTs via cp.async (L2-only path)
        {
            const float4* src = (const float4*)(hT + ((size_t)rp * 2 + dir) * (516 * 64));
            for (int idx = tid; idx < 516 * 16; idx += 512) {
                int k = idx >> 4, c = idx & 15;
                uint32_t d = hTs_b + (uint32_t)(k * 272 + c * 16);
                asm volatile("cp.async.cg.shared.global [%0], [%1], 16;"
                             :: "r"(d), "l"(src + idx));
            }
            asm volatile("cp.async.commit_group;\n\tcp.async.wait_group 0;" ::: "memory");
        }
        __syncthreads();

        // tensor-core GEMM: D[32 gate-rows x 64 b] = A[32 x 520] * hTs[520 x 64]
        float acc0[4] = {0.f, 0.f, 0.f, 0.f};
        float acc1[4] = {0.f, 0.f, 0.f, 0.f};
        for (int ch = ch_lo; ch < ch_hi; ch++) {
            int kb = ch * 8 + qid;
            uint4 af0 = *(const uint4*)&AFu[(ch * 2 + 0) * 128 + lane * 4];
            uint4 af1 = *(const uint4*)&AFu[(ch * 2 + 1) * 128 + lane * 4];
            uint32_t b0 = ((const uint32_t*)HT)[kb * 68 + n0];
            uint32_t b1 = ((const uint32_t*)HT)[(kb + 4) * 68 + n0];
            mma_tf32(acc0, af0.x, af0.y, af0.z, af0.w, b0, b1);
            mma_tf32(acc1, af1.x, af1.y, af1.z, af1.w, b0, b1);
        }
        // store D partials: gsm[kh][row][col]
        {
            float* g0 = GS + (size_t)kh * (32 * 66) + (size_t)gid * 66 + cw;
            g0[0] = acc0[0]; g0[1] = acc0[1];
            g0[8 * 66] = acc0[2]; g0[8 * 66 + 1] = acc0[3];
            float* g1 = g0 + 16 * 66;
            g1[0] = acc1[0]; g1[1] = acc1[1];
            g1[8 * 66] = acc1[2]; g1[8 * 66 + 1] = acc1[3];
        }
        __syncthreads();

        // cell
        if (cell_act) {
            const float* ga = GS + (size_t)cjj * 66 + cb;          // kh=0
            const float* gb = GS + 32 * 66 + (size_t)cjj * 66 + cb; // kh=1
            float gi = ga[0]        + gb[0]        + gxi;
            float gf = ga[8 * 66]   + gb[8 * 66]   + gxf;
            float gg = ga[16 * 66]  + gb[16 * 66]  + gxg;
            float go = ga[24 * 66]  + gb[24 * 66]  + gxo;
            float si = 1.f / (1.f + expf(-gi));
            float sf = 1.f / (1.f + expf(-gf));
            float so = 1.f / (1.f + expf(-go));
            float cn = fmaf(sf, creg, si * tanhf(gg));
            float hn = so * tanhf(cn);
            creg = cn;
            hT[((size_t)wp * 2 + dir) * (516 * 64) + (size_t)cj * 64 + cb] = hn;
            outseq[((size_t)t * B + cb) * H2 + dir * H + cj] = hn;
            if (s == T - 1) {
                dh_fin[dir * BH + cb * H + cj] = hn;
                dc_fin[dir * BH + cb * H + cj] = cn;
            }
        }

        // flat all-poll barrier (per direction)
        if (s < T - 1) {
            unsigned target = bar_base + (unsigned)(s + 1);
            __syncthreads();
            if (tid == 0) {
                __threadfence();
                *(volatile unsigned*)&slots[bx * 32] = target;
            }
            if (tid < 74) {
                volatile unsigned* sl = (volatile unsigned*)&slots[tid * 32];
                int spins = 0;
                while (*sl < target) { if (++spins > 48) __nanosleep(64); }
            }
            __syncthreads();
        }
    }
}

__global__ void dec_cell_kernel(const float* __restrict__ x, int Kx,
                                const float* __restrict__ Wi, const float* __restrict__ Wh,
                                const float* __restrict__ bias,
                                const float* __restrict__ hprev, float* __restrict__ hnext,
                                const float* __restrict__ cprev, float* __restrict__ cnext,
                                float* __restrict__ outcat, int outld) {
    const int dir = blockIdx.y;
    const int j0 = blockIdx.x * 4;
    const int tid = threadIdx.x;
    const int tx = tid & 15, ty = tid >> 4, rb = ty * 4;

    __shared__ float As[12][68];
    __shared__ float Ws[16][13];
    __shared__ float gsm[64][17];

    float acc0 = 0.f, acc1 = 0.f, acc2 = 0.f, acc3 = 0.f;

    for (int ph = 0; ph < 2; ph++) {
        const float* A = (ph == 0) ? x : (hprev + dir * BH);
        const int K = (ph == 0) ? Kx : H;
        const float* W = (ph == 0) ? (Wi + (size_t)dir * G4 * Kx) : (Wh + (size_t)dir * G4 * H);
        for (int k0 = 0; k0 < K; k0 += 12) {
            int rem = K - k0; if (rem > 12) rem = 12;
            for (int idx = tid; idx < 64 * 12; idx += 256) {
                int bb = idx / 12, kk = idx % 12;
                As[kk][bb] = (kk < rem) ? A[bb * K + k0 + kk] : 0.f;
            }
            if (tid < 192) {
                int r = tid / 12, kk = tid % 12;
                int rq = r >> 2, ru = r & 3;
                float wv = 0.f;
                if (kk < rem) wv = W[(size_t)(rq * H + j0 + ru) * K + k0 + kk];
                Ws[r][kk] = wv;
            }
            __syncthreads();
#pragma unroll
            for (int kk = 0; kk < 12; kk++) {
                float4 hv = *(const float4*)&As[kk][rb];
                float w = Ws[tx][kk];
                acc0 = fmaf(hv.x, w, acc0);
                acc1 = fmaf(hv.y, w, acc1);
                acc2 = fmaf(hv.z, w, acc2);
                acc3 = fmaf(hv.w, w, acc3);
            }
            __syncthreads();
        }
    }
    gsm[rb + 0][tx] = acc0; gsm[rb + 1][tx] = acc1;
    gsm[rb + 2][tx] = acc2; gsm[rb + 3][tx] = acc3;
    __syncthreads();
    {
        int bb = tid >> 2, uu = tid & 3;
        int j = j0 + uu;
        const float* bz = bias + dir * G4;
        float gi = gsm[bb][uu]      + bz[j];
        float gf = gsm[bb][4 + uu]  + bz[H + j];
        float gg = gsm[bb][8 + uu]  + bz[2 * H + j];
        float go = gsm[bb][12 + uu] + bz[3 * H + j];
        float cp = cprev[dir * BH + bb * H + j];
        float si = 1.f / (1.f + expf(-gi));
        float sf = 1.f / (1.f + expf(-gf));
        float so = 1.f / (1.f + expf(-go));
        float cn = fmaf(sf, cp, si * tanhf(gg));
        float hn = so * tanhf(cn);
        cnext[dir * BH + bb * H + j] = cn;
        hnext[dir * BH + bb * H + j] = hn;
        outcat[bb * outld + dir * H + j] = hn;
    }
}

__global__ void skinny64_nt_kernel(int N, int K,
                                   const float* __restrict__ A, int lda,
                                   const float* __restrict__ W, int ldw,
                                   const float* __restrict__ bias,
                                   float* __restrict__ C, int ldc, int act) {
    __shared__ float As[16][68];
    __shared__ float Ws[16][17];
    const int tid = threadIdx.x;
    const int tx = tid & 15, ty = tid >> 4;
    const int col = blockIdx.x * 16 + tx;
    float acc[4] = {0.f, 0.f, 0.f, 0.f};
    for (int k0 = 0; k0 < K; k0 += 16) {
        for (int idx = tid; idx < 64 * 16; idx += 256) {
            int r = idx >> 4, kk = idx & 15;
            As[kk][r] = (k0 + kk < K) ? A[(size_t)r * lda + k0 + kk] : 0.f;
        }
        {
            int cix = tid & 15, kk = tid >> 4;
            int cg = blockIdx.x * 16 + cix;
            float wv = 0.f;
            if (cg < N && (k0 + kk) < K) wv = W[(size_t)cg * ldw + k0 + kk];
            Ws[cix][kk] = wv;
        }
        __syncthreads();
#pragma unroll
        for (int kk = 0; kk < 16; kk++) {
            float w = Ws[tx][kk];
            float4 a = *(const float4*)&As[kk][ty * 4];
            acc[0] = fmaf(a.x, w, acc[0]);
            acc[1] = fmaf(a.y, w, acc[1]);
            acc[2] = fmaf(a.z, w, acc[2]);
            acc[3] = fmaf(a.w, w, acc[3]);
        }
        __syncthreads();
    }
    if (col < N) {
#pragma unroll
        for (int i = 0; i < 4; i++) {
            int r = ty * 4 + i;
            float v = acc[i];
            if (bias) v += bias[col];
            if (act) v = tanhf(v);
            C[(size_t)r * ldc + col] = v;
        }
    }
}

__global__ void score_kernel(const float* __restrict__ E2, const float* __restrict__ dbuf,
                             const float* __restrict__ v, float* __restrict__ score) {
    int w = blockIdx.x * 8 + (threadIdx.x >> 5);
    int lane = threadIdx.x & 31;
    int bb = w & 63, t = w >> 6;
    const float4* e = (const float4*)(E2 + (size_t)w * H2);
    const float4* d = (const float4*)(dbuf + (size_t)bb * H2);
    const float4* vv = (const float4*)v;
    float s = 0.f;
    for (int q = lane; q < H2 / 4; q += 32) {
        float4 ev = e[q], dv = d[q], vq = vv[q];
        s = fmaf(vq.x, ftanh(ev.x + dv.x), s);
        s = fmaf(vq.y, ftanh(ev.y + dv.y), s);
        s = fmaf(vq.z, ftanh(ev.z + dv.z), s);
        s = fmaf(vq.w, ftanh(ev.w + dv.w), s);
    }
#pragma unroll
    for (int o = 16; o > 0; o >>= 1) s += __shfl_down_sync(0xffffffffu, s, o);
    if (lane == 0) score[bb * T + t] = s;
}

__global__ void attn_kernel(const float* __restrict__ score, const float* __restrict__ enc,
                            float* __restrict__ cc) {
    __shared__ float sm[T];
    __shared__ float aws[T];
    int bb = blockIdx.x, tid = threadIdx.x;
    float v = score[bb * T + tid];
    sm[tid] = v;
    __syncthreads();
    for (int st = 256; st > 0; st >>= 1) {
        if (tid < st) sm[tid] = fmaxf(sm[tid], sm[tid + st]);
        __syncthreads();
    }
    float mx = sm[0];
    __syncthreads();
    float e = expf(v - mx);
    sm[tid] = e;
    __syncthreads();
    for (int st = 256; st > 0; st >>= 1) {
        if (tid < st) sm[tid] += sm[tid + st];
        __syncthreads();
    }
    aws[tid] = e / sm[0];
    __syncthreads();
    float acc[3] = {0.f, 0.f, 0.f};
    for (int t = 0; t < T; t++) {
        float wt = aws[t];
        const float* ep = enc + ((size_t)t * B + bb) * H2;
#pragma unroll
        for (int j = 0; j < 3; j++) {
            int hh = tid + j * 512;
            if (hh < H2) acc[j] = fmaf(wt, ep[hh], acc[j]);
        }
    }
#pragma unroll
    for (int j = 0; j < 3; j++) {
        int hh = tid + j * 512;
        if (hh < H2) cc[bb * (2 * H2) + H2 + hh] = acc[j];
    }
}

__global__ void ce_fused_kernel(const float* __restrict__ co, const float* __restrict__ out_W,
                                const float* __restrict__ out_b, const int* __restrict__ lab,
                                float* __restrict__ loss) {
    __shared__ float lg[64][20];
    __shared__ float red[64];
    int tid = threadIdx.x;
    int bb = tid >> 4, slot = tid & 15;
    for (int cix = slot; cix < SEQ; cix += 16) {
        const float* a = co + bb * H2;
        const float* w = out_W + cix * H2;
        float s = out_b[cix];
#pragma unroll 4
        for (int k = 0; k < H2; k++) s = fmaf(a[k], w[k], s);
        lg[bb][cix] = s;
    }
    __syncthreads();
    if (slot == 0) {
        float m = lg[bb][0];
#pragma unroll
        for (int i = 1; i < SEQ; i++) m = fmaxf(m, lg[bb][i]);
        float s = 0.f;
#pragma unroll
        for (int i = 0; i < SEQ; i++) s += expf(lg[bb][i] - m);
        red[bb] = -(lg[bb][lab[bb]] - m - logf(s));
    }
    __syncthreads();
    if (tid == 0) {
        float tot = 0.f;
        for (int i = 0; i < 64; i++) tot += red[i];
        loss[0] += tot / 64.f;
    }
}

static float* symaddr(const void* devsym) {
    void* p = nullptr;
    cudaGetSymbolAddress(&p, devsym);
    return (float*)p;
}

extern "C" void kernel_launch(void* const* d_in, const int* in_sizes, int n_in,
                              void* d_out, int out_size) {
    (void)in_sizes; (void)n_in; (void)out_size;
    const float* x        = (const float*)d_in[0];
    const float* y        = (const float*)d_in[1];
    const int*   label    = (const int*)d_in[2];
    const float* expand_W = (const float*)d_in[3];
    const float* expand_b = (const float*)d_in[4];
    const float* eWi0     = (const float*)d_in[5];
    const float* eWh0     = (const float*)d_in[6];
    const float* eb0      = (const float*)d_in[7];
    const float* eWi1     = (const float*)d_in[8];
    const float* eWh1     = (const float*)d_in[9];
    const float* eb1      = (const float*)d_in[10];
    const float* dWi0     = (const float*)d_in[11];
    const float* dWh0     = (const float*)d_in[12];
    const float* db0      = (const float*)d_in[13];
    const float* dWi1     = (const float*)d_in[14];
    const float* dWh1     = (const float*)d_in[15];
    const float* db1      = (const float*)d_in[16];
    const float* attn_W   = (const float*)d_in[17];
    const float* attn_b   = (const float*)d_in[18];
    const float* attn_v   = (const float*)d_in[19];
    const float* concat_W = (const float*)d_in[20];
    const float* concat_b = (const float*)d_in[21];
    const float* out_W    = (const float*)d_in[22];
    const float* out_b    = (const float*)d_in[23];

    float* Gx     = symaddr(&g_Gx);
    float* out0   = symaddr(&g_out0);
    float* outenc = symaddr(&g_outenc);
    float* E2     = symaddr(&g_E2);
    float* Wc     = symaddr(&g_Wc);
    float* bc     = symaddr(&g_bc);
    float* hT     = symaddr(&g_hT);
    float* dh     = symaddr(&g_dh);
    float* dc     = symaddr(&g_dc);
    float* l0     = symaddr(&g_l0);
    float* cc     = symaddr(&g_cc);
    float* dbuf   = symaddr(&g_dbuf);
    float* co     = symaddr(&g_co);
    float* score  = symaddr(&g_score);
    float* loss   = symaddr(&g_loss);
    unsigned* bar = (unsigned*)symaddr(&g_bar);

    cudaFuncSetAttribute(enc_persist3, cudaFuncAttributeMaxDynamicSharedMemorySize,
                         ENC_SMEM_BYTES);

    const int S4 = 4 * BH;
    const int HT0 = 2 * 516 * 64;

    // Launch order keeps enc_persist3 as our launch #3 (ncu -s 5 -c 1 capture slot).
    fold0_kernel<<<(G8 + 127) / 128, 128>>>(eWi0, expand_W, expand_b, eb0, Wc, bc);  // #0
    gx0_kernel<<<dim3(33, TB / 64), 256>>>(x, Wc, bc, Gx);                           // #1
    zero_all_kernel<<<(HT0 + 255) / 256, 256>>>(loss, bar, hT);                      // #2
    enc_persist3<<<dim3(74, 2), 512, ENC_SMEM_BYTES>>>(                              // #3
        Gx, eWh0, hT, out0, dh, dc, 0u);

    mma_nt_kernel<<<dim3((G8 + 127) / 128, TB / 128), 256>>>(
        TB, G8, H2, out0, H2, eWi1, H2, eb1, Gx, G8);
    zero_kernel<<<(HT0 + 255) / 256, 256>>>(hT, HT0);
    enc_persist3<<<dim3(74, 2), 512, ENC_SMEM_BYTES>>>(
        Gx, eWh1, hT, outenc, dh + 2 * BH, dc + 2 * BH, (unsigned)T);

    mma_nt_kernel<<<dim3((H2 + 127) / 128, TB / 128), 256>>>(
        TB, H2, H2, outenc, H2, attn_W + H2, G4, attn_b, E2, H2);

    for (int ts = 0; ts < NY; ts++) {
        int pp = (ts & 1) * S4, np = ((ts + 1) & 1) * S4;
        dec_cell_kernel<<<dim3(129, 2), 256>>>(
            y + (size_t)ts * B * SEQ, SEQ, dWi0, dWh0, db0,
            dh + pp, dh + np, dc + pp, dc + np, l0, H2);
        dec_cell_kernel<<<dim3(129, 2), 256>>>(
            l0, H2, dWi1, dWh1, db1,
            dh + pp + 2 * BH, dh + np + 2 * BH, dc + pp + 2 * BH, dc + np + 2 * BH,
            cc, 2 * H2);
        skinny64_nt_kernel<<<(H2 + 15) / 16, 256>>>(
            H2, H2, cc, 2 * H2, attn_W, G4, nullptr, dbuf, H2, 0);
        score_kernel<<<TB / 8, 256>>>(E2, dbuf, attn_v, score);
        attn_kernel<<<B, 512>>>(score, outenc, cc);
        skinny64_nt_kernel<<<(H2 + 15) / 16, 256>>>(
            H2, G4, cc, 2 * H2, concat_W, G4, concat_b, co, H2, 1);
        ce_fused_kernel<<<1, 1024>>>(co, out_W, out_b, label + ts * B, loss);
    }

    write_out_kernel<<<1, 1>>>((float*)d_out, loss);
}

// round 16
// speedup vs baseline: 1.5101x; 1.0825x over previous
#include <cuda_runtime.h>
#include <math.h>
#include <stdint.h>

#define H   516
#define T   512
#define B   64
#define NY  20
#define SEQ 20
#define G4  2064
#define H2  1032
#define TB  32768
#define G8  4128
#define BH  33024

#define BARSZ 4800   /* 2*74*32 slots (+ spare) */

// enc dynamic smem carve (floats)
#define OFF_AF 0                       /* A fragments: 65 ch * 2 mt * 32 lane * 4 */
#define SZ_AF  (65 * 2 * 32 * 4)
#define OFF_HT (OFF_AF + SZ_AF)        /* hTs: 520 rows * 64 cols (contiguous, swizzled) */
#define SZ_HT  (520 * 64)
#define OFF_GS (OFF_HT + SZ_HT)        /* gsm: 2 kh * 32 rows * 66 */
#define SZ_GS  (2 * 32 * 66)
#define OFF_MB (OFF_GS + SZ_GS)        /* mbarrier (8 bytes) */
#define ENC_SMEM_FLOATS (OFF_MB + 4)
#define ENC_SMEM_BYTES  (ENC_SMEM_FLOATS * 4)

#define HT_BYTES 132096u               /* 516*64*4 */

typedef unsigned long long ULL;

__device__ float g_Gx[TB * G8];
__device__ float g_out0[TB * H2];
__device__ float g_outenc[TB * H2];
__device__ float g_E2[TB * H2];
__device__ float g_Wc[G8 * 4];
__device__ float g_bc[G8];
__device__ float g_hT[2 * 2 * 516 * 64];    // [parity][dir][k][b^swz]
__device__ float g_dh[2 * 4 * BH];
__device__ float g_dc[2 * 4 * BH];
__device__ float g_l0[B * H2];
__device__ float g_cc[B * 2 * H2];
__device__ float g_dbuf[B * H2];
__device__ float g_co[B * H2];
__device__ float g_score[B * T];
__device__ float g_loss[1];
__device__ unsigned g_bar[BARSZ];

__device__ __forceinline__ uint32_t to_tf32(float x) {
    uint32_t r; asm("cvt.rna.tf32.f32 %0, %1;" : "=r"(r) : "f"(x)); return r;
}
__device__ __forceinline__ float ftanh(float x) {
    float r; asm("tanh.approx.f32 %0, %1;" : "=f"(r) : "f"(x)); return r;
}
__device__ __forceinline__ uint32_t smem_u32(const void* p) {
    uint32_t a;
    asm("{ .reg .u64 t; cvta.to.shared.u64 t, %1; cvt.u32.u64 %0, t; }"
        : "=r"(a) : "l"(p));
    return a;
}
__device__ __forceinline__ void mma_tf32(float* acc, uint32_t a0, uint32_t a1,
                                         uint32_t a2, uint32_t a3,
                                         uint32_t b0, uint32_t b1) {
    asm volatile(
        "mma.sync.aligned.m16n8k8.row.col.f32.tf32.tf32.f32 "
        "{%0,%1,%2,%3}, {%4,%5,%6,%7}, {%8,%9}, {%0,%1,%2,%3};"
        : "+f"(acc[0]), "+f"(acc[1]), "+f"(acc[2]), "+f"(acc[3])
        : "r"(a0), "r"(a1), "r"(a2), "r"(a3), "r"(b0), "r"(b1));
}
__device__ __forceinline__ void mbar_wait(uint32_t mb, uint32_t par) {
    uint32_t done;
    asm volatile(
        "{\n\t.reg .pred p;\n\t"
        "mbarrier.try_wait.parity.acquire.cta.shared::cta.b64 p, [%1], %2;\n\t"
        "selp.b32 %0, 1, 0, p;\n\t}"
        : "=r"(done) : "r"(mb), "r"(par) : "memory");
    while (!done) {
        asm volatile(
            "{\n\t.reg .pred p;\n\t"
            "mbarrier.try_wait.parity.acquire.cta.shared::cta.b64 p, [%1], %2, 0x989680;\n\t"
            "selp.b32 %0, 1, 0, p;\n\t}"
            : "=r"(done) : "r"(mb), "r"(par) : "memory");
    }
}

__global__ void zero_kernel(float* p, int n) {
    int i = blockIdx.x * 256 + threadIdx.x;
    if (i < n) p[i] = 0.f;
}
__global__ void zero_all_kernel(float* loss, unsigned* bar, float* hT) {
    int i = blockIdx.x * 256 + threadIdx.x;
    if (i == 0) loss[0] = 0.f;
    if (i < BARSZ) bar[i] = 0u;
    if (i < 2 * 516 * 64) hT[i] = 0.f;
}
__global__ void write_out_kernel(float* out, const float* loss) { out[0] = loss[0]; }

__global__ void fold0_kernel(const float* __restrict__ eWi0, const float* __restrict__ We,
                             const float* __restrict__ be, const float* __restrict__ eb0,
                             float* __restrict__ Wc, float* __restrict__ bc) {
    int i = blockIdx.x * 128 + threadIdx.x;
    if (i >= G8) return;
    const float* wi = eWi0 + (size_t)i * 256;
    float a0 = 0.f, a1 = 0.f, a2 = 0.f, a3 = 0.f, ab = eb0[i];
    for (int k = 0; k < 256; k++) {
        float w = wi[k];
        float4 we4 = *(const float4*)(We + k * 4);
        a0 = fmaf(w, we4.x, a0); a1 = fmaf(w, we4.y, a1);
        a2 = fmaf(w, we4.z, a2); a3 = fmaf(w, we4.w, a3);
        ab = fmaf(w, be[k], ab);
    }
    *(float4*)(Wc + (size_t)i * 4) = make_float4(a0, a1, a2, a3);
    bc[i] = ab;
}

__global__ void gx0_kernel(const float* __restrict__ x, const float* __restrict__ Wc,
                           const float* __restrict__ bc, float* __restrict__ Gx) {
    __shared__ float4 xs[64];
    __shared__ float4 ws[128];
    __shared__ float bs[128];
    int tid = threadIdx.x;
    int r0 = blockIdx.y * 64, c0 = blockIdx.x * 128;
    if (tid < 64) xs[tid] = *(const float4*)(x + (size_t)(r0 + tid) * 4);
    if (tid >= 128) {
        int q = tid - 128; int c = c0 + q;
        if (c < G8) { ws[q] = *(const float4*)(Wc + (size_t)c * 4); bs[q] = bc[c]; }
        else { ws[q] = make_float4(0.f, 0.f, 0.f, 0.f); bs[q] = 0.f; }
    }
    __syncthreads();
    int tc = (tid & 31) * 4, tr = (tid >> 5) * 8;
    int cg = c0 + tc;
    if (cg >= G8) return;
    float4 w0 = ws[tc], w1 = ws[tc + 1], w2 = ws[tc + 2], w3 = ws[tc + 3];
    float b0 = bs[tc], b1 = bs[tc + 1], b2 = bs[tc + 2], b3 = bs[tc + 3];
#pragma unroll
    for (int i = 0; i < 8; i++) {
        int r = r0 + tr + i;
        float4 xv = xs[tr + i];
        float4 o;
        o.x = fmaf(xv.x, w0.x, fmaf(xv.y, w0.y, fmaf(xv.z, w0.z, fmaf(xv.w, w0.w, b0))));
        o.y = fmaf(xv.x, w1.x, fmaf(xv.y, w1.y, fmaf(xv.z, w1.z, fmaf(xv.w, w1.w, b1))));
        o.z = fmaf(xv.x, w2.x, fmaf(xv.y, w2.y, fmaf(xv.z, w2.z, fmaf(xv.w, w2.w, b2))));
        o.w = fmaf(xv.x, w3.x, fmaf(xv.y, w3.y, fmaf(xv.z, w3.z, fmaf(xv.w, w3.w, b3))));
        *(float4*)(Gx + (size_t)r * G8 + cg) = o;
    }
}

// TF32 MMA GEMM: C = A @ Bm^T + bias (feed-forward path, unchanged)
__global__ void __launch_bounds__(256, 2)
mma_nt_kernel(int M, int N, int K,
              const float* __restrict__ A, int lda,
              const float* __restrict__ Bm, int ldb,
              const float* __restrict__ bias,
              float* __restrict__ C, int ldc) {
    __shared__ uint32_t As[2][16][132];
    __shared__ uint32_t Bs[2][16][132];
    const int tid = threadIdx.x;
    const int lane = tid & 31, warp = tid >> 5;
    const int gid = lane >> 2, qid = lane & 3;
    const int wm = (warp & 1) * 64, wn = (warp >> 1) * 32;
    const int row0 = blockIdx.y * 128, col0 = blockIdx.x * 128;

    float acc[4][4][4];
#pragma unroll
    for (int mt = 0; mt < 4; mt++)
#pragma unroll
        for (int nt = 0; nt < 4; nt++)
#pragma unroll
            for (int i = 0; i < 4; i++) acc[mt][nt][i] = 0.f;

    const int nk = (K + 15) / 16;
    float4 stA[2], stB[2];

    auto LOADG = [&](int ch) {
        int k0 = ch * 16;
#pragma unroll
        for (int i = 0; i < 2; i++) {
            int q = tid * 2 + i;
            int r = q >> 2, c = (q & 3) * 4;
            if (k0 + c + 3 < K) {
                stA[i] = *(const float4*)(A + (size_t)(row0 + r) * lda + k0 + c);
            } else {
                float tmp[4];
#pragma unroll
                for (int j = 0; j < 4; j++)
                    tmp[j] = (k0 + c + j < K) ? A[(size_t)(row0 + r) * lda + k0 + c + j] : 0.f;
                stA[i] = *(float4*)tmp;
            }
            int n = col0 + r;
            if (n < N && k0 + c + 3 < K) {
                stB[i] = *(const float4*)(Bm + (size_t)n * ldb + k0 + c);
            } else {
                float tmp[4];
#pragma unroll
                for (int j = 0; j < 4; j++)
                    tmp[j] = (n < N && k0 + c + j < K) ? Bm[(size_t)n * ldb + k0 + c + j] : 0.f;
                stB[i] = *(float4*)tmp;
            }
        }
    };
    auto STORE = [&](int buf) {
#pragma unroll
        for (int i = 0; i < 2; i++) {
            int q = tid * 2 + i;
            int r = q >> 2, c = (q & 3) * 4;
            const float* va = (const float*)&stA[i];
            const float* vb = (const float*)&stB[i];
#pragma unroll
            for (int j = 0; j < 4; j++) {
                As[buf][c + j][r] = to_tf32(va[j]);
                Bs[buf][c + j][r] = to_tf32(vb[j]);
            }
        }
    };
    auto COMPUTE = [&](int buf) {
#pragma unroll
        for (int ks = 0; ks < 2; ks++) {
            const int kb = ks * 8 + qid;
            uint32_t af[4][4], bf[4][2];
#pragma unroll
            for (int mt = 0; mt < 4; mt++) {
                int m0 = wm + mt * 16 + gid;
                af[mt][0] = As[buf][kb][m0];     af[mt][1] = As[buf][kb][m0 + 8];
                af[mt][2] = As[buf][kb + 4][m0]; af[mt][3] = As[buf][kb + 4][m0 + 8];
            }
#pragma unroll
            for (int nt = 0; nt < 4; nt++) {
                int n0 = wn + nt * 8 + gid;
                bf[nt][0] = Bs[buf][kb][n0]; bf[nt][1] = Bs[buf][kb + 4][n0];
            }
#pragma unroll
            for (int mt = 0; mt < 4; mt++)
#pragma unroll
                for (int nt = 0; nt < 4; nt++)
                    mma_tf32(acc[mt][nt], af[mt][0], af[mt][1], af[mt][2], af[mt][3],
                             bf[nt][0], bf[nt][1]);
        }
    };

    LOADG(0); STORE(0); __syncthreads();
    for (int ch = 0; ch < nk; ch++) {
        if (ch + 1 < nk) LOADG(ch + 1);
        COMPUTE(ch & 1);
        if (ch + 1 < nk) STORE((ch + 1) & 1);
        __syncthreads();
    }
#pragma unroll
    for (int mt = 0; mt < 4; mt++) {
        int r1 = row0 + wm + mt * 16 + gid;
#pragma unroll
        for (int nt = 0; nt < 4; nt++) {
            int c0 = col0 + wn + nt * 8 + qid * 2;
            float b0 = 0.f, b1 = 0.f;
            if (bias) {
                if (c0 < N) b0 = bias[c0];
                if (c0 + 1 < N) b1 = bias[c0 + 1];
            }
            if (c0 < N) {
                C[(size_t)r1 * ldc + c0] = acc[mt][nt][0] + b0;
                C[(size_t)(r1 + 8) * ldc + c0] = acc[mt][nt][2] + b0;
            }
            if (c0 + 1 < N) {
                C[(size_t)r1 * ldc + c0 + 1] = acc[mt][nt][1] + b1;
                C[(size_t)(r1 + 8) * ldc + c0 + 1] = acc[mt][nt][3] + b1;
            }
        }
    }
}

// persistent encoder v4: bulk-copy (TMA) staging + tensor-core GEMM + flat barrier.
// grid (74, 2 dirs), 512 threads, 1 block/SM. hT global layout is column-swizzled:
// element (k, b) lives at hT[k*64 + (b ^ ((k&3)<<3))] -> conflict-free B-frag LDS.
__global__ void __launch_bounds__(512, 1)
enc_persist4(const float* __restrict__ Gx,   // [t*B+b][G8]
             const float* __restrict__ Wh,   // [2][G4][H]
             float* __restrict__ hT,         // [2 parity][2 dir][516][64] swizzled
             float* __restrict__ outseq,     // [T][B][H2]
             float* __restrict__ dh_fin,     // [2 dir][B][H]
             float* __restrict__ dc_fin,
             unsigned bar_base) {
    extern __shared__ float smem[];
    float* AF = smem + OFF_AF;            // A frags [65][2][32][4] (tf32 bits)
    float* HT = smem + OFF_HT;            // hTs [520][64] (rows 516..519 zero)
    float* GS = smem + OFF_GS;            // gsm [2][32][66]
    uint32_t* AFu = (uint32_t*)AF;
    const uint32_t* HTu = (const uint32_t*)HT;

    const int dir = blockIdx.y, bx = blockIdx.x;
    const int j0 = bx * 7;
    const int tid = threadIdx.x;
    const uint32_t hTs_b = smem_u32(HT);
    const uint32_t mb = smem_u32(smem + OFF_MB);

    const int warp = tid >> 5, lane = tid & 31;
    const int gid = lane >> 2, qid = lane & 3;
    const int nt = warp & 7, kh = warp >> 3;
    const int ch_lo = kh ? 33 : 0, ch_hi = kh ? 65 : 33;
    const int n0 = nt * 8 + gid;          // logical B col
    const int n0s = n0 ^ (qid * 8);       // swizzled col (kb&3 == qid for both rows)
    const int cw = nt * 8 + qid * 2;      // D col base

    const int cb = tid & 63, cjj = tid >> 6;   // cell mapping
    const int cj = j0 + cjj;
    const bool cell_act = (cjj < 7) && (cj < H);
    const int cbs = cell_act ? (cb ^ ((cj & 3) << 3)) : 0;   // swizzled write col

    unsigned* slots = g_bar + dir * (74 * 32);

    // ---- one-time: zero hTs (incl. pad rows), build A fragments, init mbar ----
    for (int i = tid; i < SZ_HT; i += 512) HT[i] = 0.f;
    {
        const float* whd = Wh + (size_t)dir * G4 * H;
        for (int e = tid; e < 65 * 256; e += 512) {
            int ch = e >> 8;
            int rem = e & 255;
            int mt = rem >> 7;
            int l = (rem >> 2) & 31;
            int v = rem & 3;
            int lg = l >> 2, lq = l & 3;
            int k = ch * 8 + lq + ((v >= 2) ? 4 : 0);
            int r = mt * 16 + lg + ((v & 1) ? 8 : 0);
            int g = r >> 3, jj = r & 7;
            float wv = 0.f;
            if (jj < 7 && (j0 + jj) < H && k < H)
                wv = whd[(size_t)(g * H + j0 + jj) * H + k];
            AFu[e] = to_tf32(wv);
        }
    }
    if (tid == 0) {
        asm volatile("mbarrier.init.shared.b64 [%0], 1;" :: "r"(mb) : "memory");
        asm volatile("fence.proxy.async.shared::cta;" ::: "memory");
    }
    __syncthreads();

    float creg = 0.f;

    for (int s = 0; s < T; s++) {
        const int t = dir ? (T - 1 - s) : s;
        const int rp = s & 1, wp = (s + 1) & 1;

        // prefetch gate inputs (independent of h)
        float gxi = 0.f, gxf = 0.f, gxg = 0.f, gxo = 0.f;
        if (cell_act) {
            const float* gx = Gx + ((size_t)t * B + cb) * G8 + dir * G4 + cj;
            gxi = gx[0]; gxf = gx[H]; gxg = gx[2 * H]; gxo = gx[3 * H];
        }

        // stage h^T (132KB) via 4 bulk copies on the async engine
        if (tid == 0) {
            asm volatile("mbarrier.arrive.expect_tx.shared.b64 _, [%0], %1;"
                         :: "r"(mb), "r"(HT_BYTES) : "memory");
            const char* src = (const char*)(hT + ((size_t)rp * 2 + dir) * (516 * 64));
#pragma unroll
            for (int cpy = 0; cpy < 4; cpy++) {
                asm volatile(
                    "cp.async.bulk.shared::cluster.global.mbarrier::complete_tx::bytes "
                    "[%0], [%1], %2, [%3];"
                    :: "r"(hTs_b + (uint32_t)cpy * 33024u),
                       "l"(src + (size_t)cpy * 33024),
                       "r"(33024u), "r"(mb)
                    : "memory");
            }
        }
        mbar_wait(mb, (uint32_t)(s & 1));

        // tensor-core GEMM: D[32 gate-rows x 64 b] = A[32 x 520] * hTs[520 x 64]
        float acc0[4] = {0.f, 0.f, 0.f, 0.f};
        float acc1[4] = {0.f, 0.f, 0.f, 0.f};
        for (int ch = ch_lo; ch < ch_hi; ch++) {
            int kb = ch * 8 + qid;
            uint4 af0 = *(const uint4*)&AFu[(ch * 2 + 0) * 128 + lane * 4];
            uint4 af1 = *(const uint4*)&AFu[(ch * 2 + 1) * 128 + lane * 4];
            uint32_t b0 = HTu[kb * 64 + n0s];
            uint32_t b1 = HTu[(kb + 4) * 64 + n0s];
            mma_tf32(acc0, af0.x, af0.y, af0.z, af0.w, b0, b1);
            mma_tf32(acc1, af1.x, af1.y, af1.z, af1.w, b0, b1);
        }
        // store D partials: gsm[kh][row][col]
        {
            float* g0 = GS + (size_t)kh * (32 * 66) + (size_t)gid * 66 + cw;
            g0[0] = acc0[0]; g0[1] = acc0[1];
            g0[8 * 66] = acc0[2]; g0[8 * 66 + 1] = acc0[3];
            float* g1 = g0 + 16 * 66;
            g1[0] = acc1[0]; g1[1] = acc1[1];
            g1[8 * 66] = acc1[2]; g1[8 * 66 + 1] = acc1[3];
        }
        __syncthreads();

        // cell
        if (cell_act) {
            const float* ga = GS + (size_t)cjj * 66 + cb;           // kh=0
            const float* gb = GS + 32 * 66 + (size_t)cjj * 66 + cb; // kh=1
            float gi = ga[0]        + gb[0]        + gxi;
            float gf = ga[8 * 66]   + gb[8 * 66]   + gxf;
            float gg = ga[16 * 66]  + gb[16 * 66]  + gxg;
            float go = ga[24 * 66]  + gb[24 * 66]  + gxo;
            float si = 1.f / (1.f + expf(-gi));
            float sf = 1.f / (1.f + expf(-gf));
            float so = 1.f / (1.f + expf(-go));
            float cn = fmaf(sf, creg, si * tanhf(gg));
            float hn = so * tanhf(cn);
            creg = cn;
            hT[((size_t)wp * 2 + dir) * (516 * 64) + (size_t)cj * 64 + cbs] = hn;
            outseq[((size_t)t * B + cb) * H2 + dir * H + cj] = hn;
            if (s == T - 1) {
                dh_fin[dir * BH + cb * H + cj] = hn;
                dc_fin[dir * BH + cb * H + cj] = cn;
            }
        }

        // flat all-poll barrier (per direction)
        if (s < T - 1) {
            unsigned target = bar_base + (unsigned)(s + 1);
            __syncthreads();
            if (tid == 0) {
                __threadfence();
                *(volatile unsigned*)&slots[bx * 32] = target;
            }
            if (tid < 74) {
                volatile unsigned* sl = (volatile unsigned*)&slots[tid * 32];
                int spins = 0;
                while (*sl < target) { if (++spins > 48) __nanosleep(64); }
            }
            __syncthreads();
        }
    }
}

__global__ void dec_cell_kernel(const float* __restrict__ x, int Kx,
                                const float* __restrict__ Wi, const float* __restrict__ Wh,
                                const float* __restrict__ bias,
                                const float* __restrict__ hprev, float* __restrict__ hnext,
                                const float* __restrict__ cprev, float* __restrict__ cnext,
                                float* __restrict__ outcat, int outld) {
    const int dir = blockIdx.y;
    const int j0 = blockIdx.x * 4;
    const int tid = threadIdx.x;
    const int tx = tid & 15, ty = tid >> 4, rb = ty * 4;

    __shared__ float As[12][68];
    __shared__ float Ws[16][13];
    __shared__ float gsm[64][17];

    float acc0 = 0.f, acc1 = 0.f, acc2 = 0.f, acc3 = 0.f;

    for (int ph = 0; ph < 2; ph++) {
        const float* A = (ph == 0) ? x : (hprev + dir * BH);
        const int K = (ph == 0) ? Kx : H;
        const float* W = (ph == 0) ? (Wi + (size_t)dir * G4 * Kx) : (Wh + (size_t)dir * G4 * H);
        for (int k0 = 0; k0 < K; k0 += 12) {
            int rem = K - k0; if (rem > 12) rem = 12;
            for (int idx = tid; idx < 64 * 12; idx += 256) {
                int bb = idx / 12, kk = idx % 12;
                As[kk][bb] = (kk < rem) ? A[bb * K + k0 + kk] : 0.f;
            }
            if (tid < 192) {
                int r = tid / 12, kk = tid % 12;
                int rq = r >> 2, ru = r & 3;
                float wv = 0.f;
                if (kk < rem) wv = W[(size_t)(rq * H + j0 + ru) * K + k0 + kk];
                Ws[r][kk] = wv;
            }
            __syncthreads();
#pragma unroll
            for (int kk = 0; kk < 12; kk++) {
                float4 hv = *(const float4*)&As[kk][rb];
                float w = Ws[tx][kk];
                acc0 = fmaf(hv.x, w, acc0);
                acc1 = fmaf(hv.y, w, acc1);
                acc2 = fmaf(hv.z, w, acc2);
                acc3 = fmaf(hv.w, w, acc3);
            }
            __syncthreads();
        }
    }
    gsm[rb + 0][tx] = acc0; gsm[rb + 1][tx] = acc1;
    gsm[rb + 2][tx] = acc2; gsm[rb + 3][tx] = acc3;
    __syncthreads();
    {
        int bb = tid >> 2, uu = tid & 3;
        int j = j0 + uu;
        const float* bz = bias + dir * G4;
        float gi = gsm[bb][uu]      + bz[j];
        float gf = gsm[bb][4 + uu]  + bz[H + j];
        float gg = gsm[bb][8 + uu]  + bz[2 * H + j];
        float go = gsm[bb][12 + uu] + bz[3 * H + j];
        float cp = cprev[dir * BH + bb * H + j];
        float si = 1.f / (1.f + expf(-gi));
        float sf = 1.f / (1.f + expf(-gf));
        float so = 1.f / (1.f + expf(-go));
        float cn = fmaf(sf, cp, si * tanhf(gg));
        float hn = so * tanhf(cn);
        cnext[dir * BH + bb * H + j] = cn;
        hnext[dir * BH + bb * H + j] = hn;
        outcat[bb * outld + dir * H + j] = hn;
    }
}

__global__ void skinny64_nt_kernel(int N, int K,
                                   const float* __restrict__ A, int lda,
                                   const float* __restrict__ W, int ldw,
                                   const float* __restrict__ bias,
                                   float* __restrict__ C, int ldc, int act) {
    __shared__ float As[16][68];
    __shared__ float Ws[16][17];
    const int tid = threadIdx.x;
    const int tx = tid & 15, ty = tid >> 4;
    const int col = blockIdx.x * 16 + tx;
    float acc[4] = {0.f, 0.f, 0.f, 0.f};
    for (int k0 = 0; k0 < K; k0 += 16) {
        for (int idx = tid; idx < 64 * 16; idx += 256) {
            int r = idx >> 4, kk = idx & 15;
            As[kk][r] = (k0 + kk < K) ? A[(size_t)r * lda + k0 + kk] : 0.f;
        }
        {
            int cix = tid & 15, kk = tid >> 4;
            int cg = blockIdx.x * 16 + cix;
            float wv = 0.f;
            if (cg < N && (k0 + kk) < K) wv = W[(size_t)cg * ldw + k0 + kk];
            Ws[cix][kk] = wv;
        }
        __syncthreads();
#pragma unroll
        for (int kk = 0; kk < 16; kk++) {
            float w = Ws[tx][kk];
            float4 a = *(const float4*)&As[kk][ty * 4];
            acc[0] = fmaf(a.x, w, acc[0]);
            acc[1] = fmaf(a.y, w, acc[1]);
            acc[2] = fmaf(a.z, w, acc[2]);
            acc[3] = fmaf(a.w, w, acc[3]);
        }
        __syncthreads();
    }
    if (col < N) {
#pragma unroll
        for (int i = 0; i < 4; i++) {
            int r = ty * 4 + i;
            float v = acc[i];
            if (bias) v += bias[col];
            if (act) v = tanhf(v);
            C[(size_t)r * ldc + col] = v;
        }
    }
}

__global__ void score_kernel(const float* __restrict__ E2, const float* __restrict__ dbuf,
                             const float* __restrict__ v, float* __restrict__ score) {
    int w = blockIdx.x * 8 + (threadIdx.x >> 5);
    int lane = threadIdx.x & 31;
    int bb = w & 63, t = w >> 6;
    const float4* e = (const float4*)(E2 + (size_t)w * H2);
    const float4* d = (const float4*)(dbuf + (size_t)bb * H2);
    const float4* vv = (const float4*)v;
    float s = 0.f;
    for (int q = lane; q < H2 / 4; q += 32) {
        float4 ev = e[q], dv = d[q], vq = vv[q];
        s = fmaf(vq.x, ftanh(ev.x + dv.x), s);
        s = fmaf(vq.y, ftanh(ev.y + dv.y), s);
        s = fmaf(vq.z, ftanh(ev.z + dv.z), s);
        s = fmaf(vq.w, ftanh(ev.w + dv.w), s);
    }
#pragma unroll
    for (int o = 16; o > 0; o >>= 1) s += __shfl_down_sync(0xffffffffu, s, o);
    if (lane == 0) score[bb * T + t] = s;
}

__global__ void attn_kernel(const float* __restrict__ score, const float* __restrict__ enc,
                            float* __restrict__ cc) {
    __shared__ float sm[T];
    __shared__ float aws[T];
    int bb = blockIdx.x, tid = threadIdx.x;
    float v = score[bb * T + tid];
    sm[tid] = v;
    __syncthreads();
    for (int st = 256; st > 0; st >>= 1) {
        if (tid < st) sm[tid] = fmaxf(sm[tid], sm[tid + st]);
        __syncthreads();
    }
    float mx = sm[0];
    __syncthreads();
    float e = expf(v - mx);
    sm[tid] = e;
    __syncthreads();
    for (int st = 256; st > 0; st >>= 1) {
        if (tid < st) sm[tid] += sm[tid + st];
        __syncthreads();
    }
    aws[tid] = e / sm[0];
    __syncthreads();
    float acc[3] = {0.f, 0.f, 0.f};
    for (int t = 0; t < T; t++) {
        float wt = aws[t];
        const float* ep = enc + ((size_t)t * B + bb) * H2;
#pragma unroll
        for (int j = 0; j < 3; j++) {
            int hh = tid + j * 512;
            if (hh < H2) acc[j] = fmaf(wt, ep[hh], acc[j]);
        }
    }
#pragma unroll
    for (int j = 0; j < 3; j++) {
        int hh = tid + j * 512;
        if (hh < H2) cc[bb * (2 * H2) + H2 + hh] = acc[j];
    }
}

__global__ void ce_fused_kernel(const float* __restrict__ co, const float* __restrict__ out_W,
                                const float* __restrict__ out_b, const int* __restrict__ lab,
                                float* __restrict__ loss) {
    __shared__ float lg[64][20];
    __shared__ float red[64];
    int tid = threadIdx.x;
    int bb = tid >> 4, slot = tid & 15;
    for (int cix = slot; cix < SEQ; cix += 16) {
        const float* a = co + bb * H2;
        const float* w = out_W + cix * H2;
        float s = out_b[cix];
#pragma unroll 4
        for (int k = 0; k < H2; k++) s = fmaf(a[k], w[k], s);
        lg[bb][cix] = s;
    }
    __syncthreads();
    if (slot == 0) {
        float m = lg[bb][0];
#pragma unroll
        for (int i = 1; i < SEQ; i++) m = fmaxf(m, lg[bb][i]);
        float s = 0.f;
#pragma unroll
        for (int i = 0; i < SEQ; i++) s += expf(lg[bb][i] - m);
        red[bb] = -(lg[bb][lab[bb]] - m - logf(s));
    }
    __syncthreads();
    if (tid == 0) {
        float tot = 0.f;
        for (int i = 0; i < 64; i++) tot += red[i];
        loss[0] += tot / 64.f;
    }
}

static float* symaddr(const void* devsym) {
    void* p = nullptr;
    cudaGetSymbolAddress(&p, devsym);
    return (float*)p;
}

extern "C" void kernel_launch(void* const* d_in, const int* in_sizes, int n_in,
                              void* d_out, int out_size) {
    (void)in_sizes; (void)n_in; (void)out_size;
    const float* x        = (const float*)d_in[0];
    const float* y        = (const float*)d_in[1];
    const int*   label    = (const int*)d_in[2];
    const float* expand_W = (const float*)d_in[3];
    const float* expand_b = (const float*)d_in[4];
    const float* eWi0     = (const float*)d_in[5];
    const float* eWh0     = (const float*)d_in[6];
    const float* eb0      = (const float*)d_in[7];
    const float* eWi1     = (const float*)d_in[8];
    const float* eWh1     = (const float*)d_in[9];
    const float* eb1      = (const float*)d_in[10];
    const float* dWi0     = (const float*)d_in[11];
    const float* dWh0     = (const float*)d_in[12];
    const float* db0      = (const float*)d_in[13];
    const float* dWi1     = (const float*)d_in[14];
    const float* dWh1     = (const float*)d_in[15];
    const float* db1      = (const float*)d_in[16];
    const float* attn_W   = (const float*)d_in[17];
    const float* attn_b   = (const float*)d_in[18];
    const float* attn_v   = (const float*)d_in[19];
    const float* concat_W = (const float*)d_in[20];
    const float* concat_b = (const float*)d_in[21];
    const float* out_W    = (const float*)d_in[22];
    const float* out_b    = (const float*)d_in[23];

    float* Gx     = symaddr(&g_Gx);
    float* out0   = symaddr(&g_out0);
    float* outenc = symaddr(&g_outenc);
    float* E2     = symaddr(&g_E2);
    float* Wc     = symaddr(&g_Wc);
    float* bc     = symaddr(&g_bc);
    float* hT     = symaddr(&g_hT);
    float* dh     = symaddr(&g_dh);
    float* dc     = symaddr(&g_dc);
    float* l0     = symaddr(&g_l0);
    float* cc     = symaddr(&g_cc);
    float* dbuf   = symaddr(&g_dbuf);
    float* co     = symaddr(&g_co);
    float* score  = symaddr(&g_score);
    float* loss   = symaddr(&g_loss);
    unsigned* bar = (unsigned*)symaddr(&g_bar);

    cudaFuncSetAttribute(enc_persist4, cudaFuncAttributeMaxDynamicSharedMemorySize,
                         ENC_SMEM_BYTES);

    const int S4 = 4 * BH;
    const int HT0 = 2 * 516 * 64;

    // Launch order keeps enc_persist4 as our launch #3 (ncu -s 5 -c 1 capture slot).
    fold0_kernel<<<(G8 + 127) / 128, 128>>>(eWi0, expand_W, expand_b, eb0, Wc, bc);  // #0
    gx0_kernel<<<dim3(33, TB / 64), 256>>>(x, Wc, bc, Gx);                           // #1
    zero_all_kernel<<<(HT0 + 255) / 256, 256>>>(loss, bar, hT);                      // #2
    enc_persist4<<<dim3(74, 2), 512, ENC_SMEM_BYTES>>>(                              // #3
        Gx, eWh0, hT, out0, dh, dc, 0u);

    mma_nt_kernel<<<dim3((G8 + 127) / 128, TB / 128), 256>>>(
        TB, G8, H2, out0, H2, eWi1, H2, eb1, Gx, G8);
    zero_kernel<<<(HT0 + 255) / 256, 256>>>(hT, HT0);
    enc_persist4<<<dim3(74, 2), 512, ENC_SMEM_BYTES>>>(
        Gx, eWh1, hT, outenc, dh + 2 * BH, dc + 2 * BH, (unsigned)T);

    mma_nt_kernel<<<dim3((H2 + 127) / 128, TB / 128), 256>>>(
        TB, H2, H2, outenc, H2, attn_W + H2, G4, attn_b, E2, H2);

    for (int ts = 0; ts < NY; ts++) {
        int pp = (ts & 1) * S4, np = ((ts + 1) & 1) * S4;
        dec_cell_kernel<<<dim3(129, 2), 256>>>(
            y + (size_t)ts * B * SEQ, SEQ, dWi0, dWh0, db0,
            dh + pp, dh + np, dc + pp, dc + np, l0, H2);
        dec_cell_kernel<<<dim3(129, 2), 256>>>(
            l0, H2, dWi1, dWh1, db1,
            dh + pp + 2 * BH, dh + np + 2 * BH, dc + pp + 2 * BH, dc + np + 2 * BH,
            cc, 2 * H2);
        skinny64_nt_kernel<<<(H2 + 15) / 16, 256>>>(
            H2, H2, cc, 2 * H2, attn_W, G4, nullptr, dbuf, H2, 0);
        score_kernel<<<TB / 8, 256>>>(E2, dbuf, attn_v, score);
        attn_kernel<<<B, 512>>>(score, outenc, cc);
        skinny64_nt_kernel<<<(H2 + 15) / 16, 256>>>(
            H2, G4, cc, 2 * H2, concat_W, G4, concat_b, co, H2, 1);
        ce_fused_kernel<<<1, 1024>>>(co, out_W, out_b, label + ts * B, loss);
    }

    write_out_kernel<<<1, 1>>>((float*)d_out, loss);
}